// round 13
// baseline (speedup 1.0000x reference)
#include <cuda_runtime.h>
#include <cuda_bf16.h>
#include <cstdint>
#include <math.h>

// Problem constants (fixed by reference)
#define BB 2
#define LL 2048
#define DM 1024
#define DI 2048
#define DS 16
#define DR 64
#define NR (BB*LL)     // 4096 rows (b,l)
#define XZW (2*DI)     // 4096
#define XD  96         // dt_rank + 2*d_state
#define NCH 16
#define LC (LL/NCH)    // 128

// Scratch (device globals; no allocation allowed)
__device__ float g_xz  [(size_t)NR*XZW];   // in_proj output [B,L,2*DI]
__device__ float g_xpt [(size_t)BB*DI*LL]; // conv+silu output transposed [B,DI,L]
__device__ float g_xdbl[(size_t)NR*XD];    // x_proj output [B,L,96]
__device__ float g_dtt [(size_t)BB*DI*LL]; // softplus(delta) transposed [B,DI,L]
__device__ float g_yt  [(size_t)BB*DI*LL]; // scan output (+D*x) [B,DI,L]
__device__ float g_xpart[(size_t)8*NR*128];// xproj split-K partials [8][4096][128]
__device__ float g_delta[(size_t)NR*DI];   // delta GEMM output, later fp32 g
__device__ float g_q   [(size_t)(NCH-1)*BB*DI*DS]; // pass1 final states
__device__ float g_sdt [(size_t)(NCH-1)*BB*DI];    // pass1 per-chunk sum(dt)

// bf16 split buffers (xproj + delta GEMMs, still HMMA)
__device__ __nv_bfloat16 g_xphi[(size_t)NR*DI];
__device__ __nv_bfloat16 g_xplo[(size_t)NR*DI];
__device__ __nv_bfloat16 g_w3hi[(size_t)128*DI];
__device__ __nv_bfloat16 g_w3lo[(size_t)128*DI];
__device__ __nv_bfloat16 g_dthi[(size_t)NR*DR];
__device__ __nv_bfloat16 g_dtlo[(size_t)NR*DR];
__device__ __nv_bfloat16 g_wdhi[(size_t)DI*DR];
__device__ __nv_bfloat16 g_wdlo[(size_t)DI*DR];

// int8 split-quant buffers (in_proj + out_proj GEMMs, IMMA)
__device__ int8_t g_qx1 [(size_t)NR*DM];
__device__ int8_t g_qx2 [(size_t)NR*DM];
__device__ int8_t g_qw11[(size_t)XZW*DM];
__device__ int8_t g_qw12[(size_t)XZW*DM];
__device__ int8_t g_qg1 [(size_t)NR*DI];
__device__ int8_t g_qg2 [(size_t)NR*DI];
__device__ int8_t g_qw21[(size_t)DM*DI];
__device__ int8_t g_qw22[(size_t)DM*DI];
__device__ float  g_scx [NR];
__device__ float  g_scw1[XZW];
__device__ float  g_scg [NR];
__device__ float  g_scw2[DM];

__device__ __forceinline__ float siluf(float x) { return x / (1.0f + __expf(-x)); }
__device__ __forceinline__ float softplusf(float x) {
    return (x > 20.0f) ? x : log1pf(__expf(x));
}

// ===========================================================================
// Base-target (sm_103, no 'a') tensor path helpers
// ===========================================================================
__device__ __forceinline__ uint32_t smem_u32(const void* p) {
    uint32_t a;
    asm("{ .reg .u64 t; cvta.to.shared.u64 t, %1; cvt.u32.u64 %0, t; }" : "=r"(a) : "l"(p));
    return a;
}
__device__ __forceinline__ void cpa16(uint32_t dst, const void* src) {
    asm volatile("cp.async.cg.shared.global [%0], [%1], 16;" :: "r"(dst), "l"(src));
}
__device__ __forceinline__ void ldsm4(uint32_t* r, uint32_t a) {
    asm volatile("ldmatrix.sync.aligned.m8n8.x4.shared.b16 {%0,%1,%2,%3}, [%4];"
                 : "=r"(r[0]), "=r"(r[1]), "=r"(r[2]), "=r"(r[3]) : "r"(a));
}
__device__ __forceinline__ void mma16816(float* c, const uint32_t* a, const uint32_t* b) {
    asm volatile("mma.sync.aligned.m16n8k16.row.col.f32.bf16.bf16.f32 "
                 "{%0,%1,%2,%3}, {%4,%5,%6,%7}, {%8,%9}, {%0,%1,%2,%3};"
                 : "+f"(c[0]), "+f"(c[1]), "+f"(c[2]), "+f"(c[3])
                 : "r"(a[0]), "r"(a[1]), "r"(a[2]), "r"(a[3]), "r"(b[0]), "r"(b[1]));
}
__device__ __forceinline__ void imma16832(int* c, const uint32_t* a, const uint32_t* b) {
    asm volatile("mma.sync.aligned.m16n8k32.row.col.s32.s8.s8.s32 "
                 "{%0,%1,%2,%3}, {%4,%5,%6,%7}, {%8,%9}, {%0,%1,%2,%3};"
                 : "+r"(c[0]), "+r"(c[1]), "+r"(c[2]), "+r"(c[3])
                 : "r"(a[0]), "r"(a[1]), "r"(a[2]), "r"(a[3]), "r"(b[0]), "r"(b[1]));
}

// ===========================================================================
// Row-wise split int8 quantization: v = s*q1 + (s/256)*q2, s = 2^e
// One block (256 thr) per row; row cached in smem.
// ===========================================================================
__global__ __launch_bounds__(256)
void quant_s8(const float* __restrict__ in, int8_t* __restrict__ q1,
              int8_t* __restrict__ q2, float* __restrict__ sc, int K)
{
    __shared__ float srow[2048];
    __shared__ float red[8];
    const int row = blockIdx.x, tid = threadIdx.x;
    const float* rp = in + (size_t)row * K;

    float m = 0.f;
    for (int k = tid; k < K; k += 256) {
        float v = rp[k];
        srow[k] = v;
        m = fmaxf(m, fabsf(v));
    }
    #pragma unroll
    for (int o = 16; o; o >>= 1) m = fmaxf(m, __shfl_xor_sync(0xffffffffu, m, o));
    if ((tid & 31) == 0) red[tid >> 5] = m;
    __syncthreads();
    if (tid < 8) {
        float t = red[tid];
        #pragma unroll
        for (int o = 4; o; o >>= 1) t = fmaxf(t, __shfl_xor_sync(0xffu, t, o));
        if (tid == 0) red[0] = t;
    }
    __syncthreads();
    float mx = fmaxf(red[0], 1e-30f);
    float s1 = exp2f(ceilf(log2f(mx * (1.0f/127.0f))));
    float i1 = 1.0f / s1;
    float i2 = 256.0f / s1;
    if (tid == 0) sc[row] = s1;

    for (int k = tid; k < K; k += 256) {
        float v = srow[k];
        int a = __float2int_rn(v * i1);
        a = max(-127, min(127, a));
        float r = v - (float)a * s1;
        int b = __float2int_rn(r * i2);
        b = max(-127, min(127, b));
        q1[(size_t)row * K + k] = (int8_t)a;
        q2[(size_t)row * K + k] = (int8_t)b;
    }
}

// ===========================================================================
// Split-int8 IMMA GEMM: C[M,N] = (sa.q1+sa/256.q2)A @ B^T, s32 accumulate.
// CTA tile 64x128, 4 warps (warp tile 64x32), stage K=32 (one 32B row).
// 8-stage cp.async ring (12KB/stage), barrier per 2 stages, 2 CTAs/SM.
// D = sa[m]*sb[n]*(acc1 + accR/256); dropped q2*q2 term ~1e-4 rel.
// ===========================================================================
#define IA_LO 2048
#define IB_HI 4096
#define IB_LO 8192
#define I_STG 12288
#define I_NSTG 8
#define IM_SMEM (I_NSTG*I_STG)   // 98304/CTA -> 2 CTAs/SM

__global__ void __launch_bounds__(128, 2)
imma_gemm(const int8_t* __restrict__ A1, const int8_t* __restrict__ A2,
          const int8_t* __restrict__ B1, const int8_t* __restrict__ B2,
          const float* __restrict__ sa, const float* __restrict__ sb,
          float* __restrict__ C, int N, int K)
{
    extern __shared__ char sm_[];
    const uint32_t smb = smem_u32(sm_);
    const int tid = threadIdx.x, lane = tid & 31, wn = tid >> 5;  // 4 warps
    const int m0 = blockIdx.y * 64, n0 = blockIdx.x * 128;
    const int nst = K >> 5;

    int acc1[4][4][4], accR[4][4][4];
    #pragma unroll
    for (int i = 0; i < 4; ++i)
        #pragma unroll
        for (int j = 0; j < 4; ++j)
            #pragma unroll
            for (int q = 0; q < 4; ++q) { acc1[i][j][q] = 0; accR[i][j][q] = 0; }

    // cp.async mapping: A 64 rows (1 chunk/thread/plane), B 128 rows (2)
    const int arow = tid >> 1, ach = tid & 1;
    const uint32_t awo = (uint32_t)(arow*32 + ((ach ^ ((arow >> 2) & 1)) << 4));
    const int brow1 = 64 + arow;
    const uint32_t bwo0 = awo;
    const uint32_t bwo1 = (uint32_t)(brow1*32 + ((ach ^ ((brow1 >> 2) & 1)) << 4));
    const char* pA1 = (const char*)A1 + (size_t)(m0 + arow) * K + ach*16;
    const char* pA2 = (const char*)A2 + (size_t)(m0 + arow) * K + ach*16;
    const char* pB1a = (const char*)B1 + (size_t)(n0 + arow) * K + ach*16;
    const char* pB1b = (const char*)B1 + (size_t)(n0 + brow1) * K + ach*16;
    const char* pB2a = (const char*)B2 + (size_t)(n0 + arow) * K + ach*16;
    const char* pB2b = (const char*)B2 + (size_t)(n0 + brow1) * K + ach*16;

    auto load_stage = [&](int s) {
        if (s < nst) {
            const uint32_t st = smb + (uint32_t)(s % I_NSTG) * I_STG;
            const int kb = s * 32;
            cpa16(st + awo, pA1 + kb);
            cpa16(st + IA_LO + awo, pA2 + kb);
            cpa16(st + IB_HI + bwo0, pB1a + kb);
            cpa16(st + IB_HI + bwo1, pB1b + kb);
            cpa16(st + IB_LO + bwo0, pB2a + kb);
            cpa16(st + IB_LO + bwo1, pB2b + kb);
        }
        asm volatile("cp.async.commit_group;");
    };

    load_stage(0); load_stage(1); load_stage(2);
    load_stage(3); load_stage(4); load_stage(5);

    // ldsm offsets (swizzle invariant under +16-row steps)
    const int rA = lane & 15, cA = lane >> 4;
    const uint32_t aOff = (uint32_t)(rA*32 + ((cA ^ ((rA >> 2) & 1)) << 4));
    const int rB = wn*32 + (lane & 7) + ((lane >> 4) << 3);
    const int cB = (lane >> 3) & 1;
    const uint32_t bOff = (uint32_t)(rB*32 + ((cB ^ ((rB >> 2) & 1)) << 4));

    auto process_stage = [&](int s) {
        const uint32_t st = smb + (uint32_t)(s % I_NSTG) * I_STG;
        const uint32_t aB = st + aOff;
        const uint32_t bB = st + IB_HI + bOff;

        uint32_t a1[4][4], a2[4][4], b1[2][4], b2[2][4];
        ldsm4(b1[0], bB);
        ldsm4(b1[1], bB + 512);
        #pragma unroll
        for (int i = 0; i < 4; ++i) ldsm4(a1[i], aB + i * 512);
        #pragma unroll
        for (int i = 0; i < 4; ++i) ldsm4(a2[i], aB + IA_LO + i * 512);
        ldsm4(b2[0], bB + (IB_LO - IB_HI));
        ldsm4(b2[1], bB + (IB_LO - IB_HI) + 512);

        #pragma unroll
        for (int i = 0; i < 4; ++i)
            #pragma unroll
            for (int j = 0; j < 4; ++j)
                imma16832(acc1[i][j], a1[i], &b1[j >> 1][(j & 1) * 2]);
        #pragma unroll
        for (int i = 0; i < 4; ++i)
            #pragma unroll
            for (int j = 0; j < 4; ++j)
                imma16832(accR[i][j], a1[i], &b2[j >> 1][(j & 1) * 2]);
        #pragma unroll
        for (int i = 0; i < 4; ++i)
            #pragma unroll
            for (int j = 0; j < 4; ++j)
                imma16832(accR[i][j], a2[i], &b1[j >> 1][(j & 1) * 2]);
    };

    for (int p = 0; p < (nst >> 1); ++p) {
        asm volatile("cp.async.wait_group 4;");
        __syncthreads();
        load_stage(2*p + 6);
        load_stage(2*p + 7);
        process_stage(2*p);
        process_stage(2*p + 1);
    }

    // epilogue: combine scales, fp32 to global
    const float inv256 = 0.00390625f;
    #pragma unroll
    for (int i = 0; i < 4; ++i) {
        int row = m0 + i*16 + (lane >> 2);
        float sa0 = __ldg(sa + row), sa1 = __ldg(sa + row + 8);
        #pragma unroll
        for (int j = 0; j < 4; ++j) {
            int col = n0 + wn*32 + j*8 + (lane & 3)*2;
            float sb0 = __ldg(sb + col), sb1 = __ldg(sb + col + 1);
            *(float2*)(C + (size_t)row * N + col) = make_float2(
                sa0*sb0*((float)acc1[i][j][0] + (float)accR[i][j][0]*inv256),
                sa0*sb1*((float)acc1[i][j][1] + (float)accR[i][j][1]*inv256));
            *(float2*)(C + (size_t)(row + 8) * N + col) = make_float2(
                sa1*sb0*((float)acc1[i][j][2] + (float)accR[i][j][2]*inv256),
                sa1*sb1*((float)acc1[i][j][3] + (float)accR[i][j][3]*inv256));
        }
    }
}

// ===========================================================================
// Split fp32 -> bf16 hi + lo (dt_proj_w)
// ===========================================================================
__global__ void split_bf16(const float* __restrict__ in, __nv_bfloat16* __restrict__ hi,
                           __nv_bfloat16* __restrict__ lo, int n4)
{
    int i = blockIdx.x * blockDim.x + threadIdx.x;
    if (i >= n4) return;
    float4 v = *(const float4*)(in + (size_t)i * 4);
    __nv_bfloat16 h0 = __float2bfloat16(v.x), h1 = __float2bfloat16(v.y);
    __nv_bfloat16 h2 = __float2bfloat16(v.z), h3 = __float2bfloat16(v.w);
    __nv_bfloat162* hp = (__nv_bfloat162*)(hi + (size_t)i * 4);
    __nv_bfloat162* lp = (__nv_bfloat162*)(lo + (size_t)i * 4);
    hp[0] = __nv_bfloat162(h0, h1); hp[1] = __nv_bfloat162(h2, h3);
    lp[0] = __nv_bfloat162(__float2bfloat16(v.x - __bfloat162float(h0)),
                           __float2bfloat16(v.y - __bfloat162float(h1)));
    lp[1] = __nv_bfloat162(__float2bfloat16(v.z - __bfloat162float(h2)),
                           __float2bfloat16(v.w - __bfloat162float(h3)));
}

// Split + zero-pad x_proj_w [96,2048] -> [128,2048] bf16 hi/lo
__global__ void split_pad_xw(const float* __restrict__ xw)
{
    int i = blockIdx.x * blockDim.x + threadIdx.x;
    if (i >= 128 * DI / 4) return;
    int row = i >> 9;
    float4 v = make_float4(0.f, 0.f, 0.f, 0.f);
    if (row < 96) v = *(const float4*)(xw + (size_t)i * 4);
    __nv_bfloat16 h0 = __float2bfloat16(v.x), h1 = __float2bfloat16(v.y);
    __nv_bfloat16 h2 = __float2bfloat16(v.z), h3 = __float2bfloat16(v.w);
    __nv_bfloat162* hp = (__nv_bfloat162*)(g_w3hi + (size_t)i * 4);
    __nv_bfloat162* lp = (__nv_bfloat162*)(g_w3lo + (size_t)i * 4);
    hp[0] = __nv_bfloat162(h0, h1); hp[1] = __nv_bfloat162(h2, h3);
    lp[0] = __nv_bfloat162(__float2bfloat16(v.x - __bfloat162float(h0)),
                           __float2bfloat16(v.y - __bfloat162float(h1)));
    lp[1] = __nv_bfloat162(__float2bfloat16(v.z - __bfloat162float(h2)),
                           __float2bfloat16(v.w - __bfloat162float(h3)));
}

// ===========================================================================
// Split-bf16 HMMA GEMM v5 (unchanged — xproj + delta)
// ===========================================================================
#define OA_LO 4096
#define OB_HI 8192
#define OB_LO 12288
#define STG   16384
#define NSTG  6
#define HM_SMEM (NSTG*STG)

__global__ void __launch_bounds__(256, 2)
hmma_gemm(const __nv_bfloat16* __restrict__ Ahi, const __nv_bfloat16* __restrict__ Alo,
          const __nv_bfloat16* __restrict__ Bhi, const __nv_bfloat16* __restrict__ Blo,
          float* __restrict__ C, int N, int K, int kChunk, size_t cStride)
{
    extern __shared__ char sm_[];
    const uint32_t sb = smem_u32(sm_);
    const int tid = threadIdx.x, lane = tid & 31, wid = tid >> 5;
    const int wm = wid >> 2, wn = wid & 3;
    const int m0 = blockIdx.y * 128, n0 = blockIdx.x * 128;
    const int kOffB = blockIdx.z * kChunk * 2;
    C += (size_t)blockIdx.z * cStride;
    const int nst = kChunk >> 4;

    float acc[4][4][4];
    #pragma unroll
    for (int i = 0; i < 4; ++i)
        #pragma unroll
        for (int j = 0; j < 4; ++j)
            #pragma unroll
            for (int q = 0; q < 4; ++q) acc[i][j][q] = 0.0f;

    const int lr = wid * 16 + (lane & 7) + ((lane >> 4) << 3);
    const int ch = (lane >> 3) & 1;
    const uint32_t wo = (uint32_t)(lr * 32 + ((ch ^ ((lr >> 2) & 1)) << 4));
    const int gh = ch * 16;
    const char* pAh = (const char*)(Ahi + (size_t)(m0 + lr) * K) + kOffB + gh;
    const char* pAl = (const char*)(Alo + (size_t)(m0 + lr) * K) + kOffB + gh;
    const char* pBh = (const char*)(Bhi + (size_t)(n0 + lr) * K) + kOffB + gh;
    const char* pBl = (const char*)(Blo + (size_t)(n0 + lr) * K) + kOffB + gh;

    auto load_stage = [&](int s) {
        if (s < nst) {
            const uint32_t st = sb + (uint32_t)(s % NSTG) * STG;
            const int kb = s * 32;
            cpa16(st + wo, pAh + kb);
            cpa16(st + OA_LO + wo, pAl + kb);
            cpa16(st + OB_HI + wo, pBh + kb);
            cpa16(st + OB_LO + wo, pBl + kb);
        }
        asm volatile("cp.async.commit_group;");
    };

    load_stage(0);
    load_stage(1);
    load_stage(2);
    load_stage(3);

    const int rowA = wm * 64 + (lane & 15);
    const int cA = lane >> 4;
    const uint32_t aOff = (uint32_t)(rowA * 32 + ((cA ^ ((rowA >> 2) & 1)) << 4));
    const int rowB = wn * 32 + (lane & 7) + ((lane >> 4) << 3);
    const int cB = (lane >> 3) & 1;
    const uint32_t bOff = (uint32_t)(rowB * 32 + ((cB ^ ((rowB >> 2) & 1)) << 4));

    auto process_stage = [&](int s) {
        const uint32_t st = sb + (uint32_t)(s % NSTG) * STG;
        const uint32_t aB = st + aOff;
        const uint32_t bB = st + OB_HI + bOff;

        uint32_t ah[4][4], al[4][4], bh[2][4], bl[2][4];
        ldsm4(bh[0], bB);
        ldsm4(bh[1], bB + 512);
        #pragma unroll
        for (int i = 0; i < 4; ++i) ldsm4(ah[i], aB + i * 512);
        #pragma unroll
        for (int i = 0; i < 4; ++i) ldsm4(al[i], aB + OA_LO + i * 512);
        ldsm4(bl[0], bB + (OB_LO - OB_HI));
        ldsm4(bl[1], bB + (OB_LO - OB_HI) + 512);

        #pragma unroll
        for (int i = 0; i < 4; ++i)
            #pragma unroll
            for (int j = 0; j < 4; ++j)
                mma16816(acc[i][j], ah[i], &bh[j >> 1][(j & 1) * 2]);
        #pragma unroll
        for (int i = 0; i < 4; ++i)
            #pragma unroll
            for (int j = 0; j < 4; ++j)
                mma16816(acc[i][j], al[i], &bh[j >> 1][(j & 1) * 2]);
        #pragma unroll
        for (int i = 0; i < 4; ++i)
            #pragma unroll
            for (int j = 0; j < 4; ++j)
                mma16816(acc[i][j], ah[i], &bl[j >> 1][(j & 1) * 2]);
    };

    for (int p = 0; p < (nst >> 1); ++p) {
        asm volatile("cp.async.wait_group 2;");
        __syncthreads();
        load_stage(2*p + 4);
        load_stage(2*p + 5);
        process_stage(2*p);
        process_stage(2*p + 1);
    }

    #pragma unroll
    for (int i = 0; i < 4; ++i)
        #pragma unroll
        for (int j = 0; j < 4; ++j) {
            int row = m0 + wm*64 + i*16 + (lane >> 2);
            int col = n0 + wn*32 + j*8 + (lane & 3)*2;
            *(float2*)(C + (size_t)row * N + col) =
                make_float2(acc[i][j][0], acc[i][j][1]);
            *(float2*)(C + (size_t)(row + 8) * N + col) =
                make_float2(acc[i][j][2], acc[i][j][3]);
        }
}

// Reduce xproj split-K partials; also emits bf16 hi/lo of delta cols 0..63
__global__ void reduce_xdbl()
{
    int idx = blockIdx.x * blockDim.x + threadIdx.x;
    if (idx >= NR * 24) return;
    int m = idx / 24, c = (idx % 24) * 4;
    const float* p = g_xpart + (size_t)m * 128 + c;
    float4 s = make_float4(0.f, 0.f, 0.f, 0.f);
    #pragma unroll
    for (int z = 0; z < 8; ++z) {
        float4 v = *(const float4*)(p + (size_t)z * NR * 128);
        s.x += v.x; s.y += v.y; s.z += v.z; s.w += v.w;
    }
    *(float4*)(g_xdbl + (size_t)m * XD + c) = s;
    if (c < DR) {
        __nv_bfloat16 h0 = __float2bfloat16(s.x), h1 = __float2bfloat16(s.y);
        __nv_bfloat16 h2 = __float2bfloat16(s.z), h3 = __float2bfloat16(s.w);
        __nv_bfloat162* hp = (__nv_bfloat162*)(g_dthi + (size_t)m * DR + c);
        __nv_bfloat162* lp = (__nv_bfloat162*)(g_dtlo + (size_t)m * DR + c);
        hp[0] = __nv_bfloat162(h0, h1); hp[1] = __nv_bfloat162(h2, h3);
        lp[0] = __nv_bfloat162(__float2bfloat16(s.x - __bfloat162float(h0)),
                               __float2bfloat16(s.y - __bfloat162float(h1)));
        lp[1] = __nv_bfloat162(__float2bfloat16(s.z - __bfloat162float(h2)),
                               __float2bfloat16(s.w - __bfloat162float(h3)));
    }
}

// ---------------------------------------------------------------------------
// Causal depthwise conv + bias + silu; bf16 hi/lo + fp32 transposed outputs.
// ---------------------------------------------------------------------------
__global__ void conv_silu_kernel(const float* __restrict__ conv_w,
                                 const float* __restrict__ conv_b)
{
    __shared__ float sIn[35][33];
    __shared__ float sOut[32][33];
    const int b = blockIdx.z, d0 = blockIdx.y * 32, l0 = blockIdx.x * 32;
    const int tid = threadIdx.x, tx = tid & 31, ty = tid >> 5;

    for (int r = ty; r < 35; r += 8) {
        int gl = l0 + r - 3;
        sIn[r][tx] = (gl >= 0) ? g_xz[(size_t)(b*LL + gl) * XZW + d0 + tx] : 0.0f;
    }
    __syncthreads();

    float4 w = *(const float4*)(conv_w + (d0 + tx) * 4);
    float cb = conv_b[d0 + tx];
    #pragma unroll
    for (int i = 0; i < 4; ++i) {
        int r = ty + i * 8;
        float v = sIn[r][tx]*w.x + sIn[r+1][tx]*w.y + sIn[r+2][tx]*w.z + sIn[r+3][tx]*w.w + cb;
        v = siluf(v);
        sOut[r][tx] = v;
        size_t idx = (size_t)(b*LL + l0 + r) * DI + d0 + tx;
        __nv_bfloat16 h = __float2bfloat16(v);
        g_xphi[idx] = h;
        g_xplo[idx] = __float2bfloat16(v - __bfloat162float(h));
    }
    __syncthreads();
    #pragma unroll
    for (int i = 0; i < 4; ++i) {
        int dd = ty + i * 8;
        g_xpt[(size_t)(b*DI + d0 + dd) * LL + l0 + tx] = sOut[tx][dd];
    }
}

// ---------------------------------------------------------------------------
// delta transpose + bias + softplus
// ---------------------------------------------------------------------------
__global__ void dtrans_kernel(const float* __restrict__ dtb)
{
    __shared__ float sD[32][33];
    const int b = blockIdx.z, n0 = blockIdx.y * 32, l0 = blockIdx.x * 32;
    const int tid = threadIdx.x, tx = tid & 31, ty = tid >> 5;

    #pragma unroll
    for (int i = 0; i < 4; ++i) {
        int r = ty + i * 8;
        sD[r][tx] = g_delta[(size_t)(b*LL + l0 + r) * DI + n0 + tx];
    }
    __syncthreads();
    #pragma unroll
    for (int i = 0; i < 4; ++i) {
        int ny = ty + i * 8;
        int n = n0 + ny;
        float v = softplusf(sD[tx][ny] + dtb[n]);
        g_dtt[(size_t)(b*DI + n) * LL + l0 + tx] = v;
    }
}

// ---------------------------------------------------------------------------
// Chunked selective scan, pass 1
// ---------------------------------------------------------------------------
__global__ __launch_bounds__(256)
void scan_pass1(const float* __restrict__ A_log)
{
    const int tid = threadIdx.x;
    const int ch = blockIdx.x * 32 + (tid >> 3);
    const int g  = tid & 7;
    const int c  = blockIdx.y;
    const int d  = ch & (DI - 1);
    const int b  = ch >> 11;
    const int n0 = g * 2;

    const float A0 = -__expf(A_log[d*DS + n0]);
    const float A1 = -__expf(A_log[d*DS + n0 + 1]);

    const float* __restrict__ dtp = g_dtt + (size_t)ch * LL + c * LC;
    const float* __restrict__ xpp = g_xpt + (size_t)ch * LL + c * LC;
    const float* __restrict__ rp  = g_xdbl + (size_t)(b*LL + c*LC) * XD + DR + n0;

    float h0 = 0.f, h1 = 0.f, sdt = 0.f;
    float dt[2][4], xv[2][4];
    float2 Bv[2][4];

    #pragma unroll
    for (int u = 0; u < 4; ++u) {
        dt[0][u] = __ldg(dtp + u);
        xv[0][u] = __ldg(xpp + u);
        Bv[0][u] = *(const float2*)(rp + (size_t)u * XD);
    }

    for (int l = 0; l < LC; l += 8) {
        #pragma unroll
        for (int u = 0; u < 4; ++u) {
            int ll = l + 4 + u;
            dt[1][u] = __ldg(dtp + ll);
            xv[1][u] = __ldg(xpp + ll);
            Bv[1][u] = *(const float2*)(rp + (size_t)ll * XD);
        }
        #pragma unroll
        for (int u = 0; u < 4; ++u) {
            float dtx = dt[0][u] * xv[0][u];
            h0 = fmaf(__expf(dt[0][u] * A0), h0, dtx * Bv[0][u].x);
            h1 = fmaf(__expf(dt[0][u] * A1), h1, dtx * Bv[0][u].y);
            sdt += dt[0][u];
        }
        int lp = (l + 8 < LC) ? l + 8 : 0;
        #pragma unroll
        for (int u = 0; u < 4; ++u) {
            int ll = lp + u;
            dt[0][u] = __ldg(dtp + ll);
            xv[0][u] = __ldg(xpp + ll);
            Bv[0][u] = *(const float2*)(rp + (size_t)ll * XD);
        }
        #pragma unroll
        for (int u = 0; u < 4; ++u) {
            float dtx = dt[1][u] * xv[1][u];
            h0 = fmaf(__expf(dt[1][u] * A0), h0, dtx * Bv[1][u].x);
            h1 = fmaf(__expf(dt[1][u] * A1), h1, dtx * Bv[1][u].y);
            sdt += dt[1][u];
        }
    }

    float* qp = g_q + ((size_t)c * (BB*DI) + ch) * DS + n0;
    qp[0] = h0; qp[1] = h1;
    if (g == 0) g_sdt[(size_t)c * (BB*DI) + ch] = sdt;
}

// ---------------------------------------------------------------------------
// Chunked selective scan, pass 2
// ---------------------------------------------------------------------------
__global__ __launch_bounds__(256)
void scan_pass2(const float* __restrict__ A_log, const float* __restrict__ Dv)
{
    const int tid = threadIdx.x;
    const int ch = blockIdx.x * 32 + (tid >> 3);
    const int g  = tid & 7;
    const int c  = blockIdx.y;
    const int d  = ch & (DI - 1);
    const int b  = ch >> 11;
    const int n0 = g * 2;

    const float A0 = -__expf(A_log[d*DS + n0]);
    const float A1 = -__expf(A_log[d*DS + n0 + 1]);
    const float Dd = Dv[d];

    float h0 = 0.f, h1 = 0.f;
    for (int j = 0; j < c; ++j) {
        float s = __ldg(g_sdt + (size_t)j * (BB*DI) + ch);
        const float* qp = g_q + ((size_t)j * (BB*DI) + ch) * DS + n0;
        h0 = fmaf(__expf(s * A0), h0, __ldg(qp));
        h1 = fmaf(__expf(s * A1), h1, __ldg(qp + 1));
    }

    const float* __restrict__ dtp = g_dtt + (size_t)ch * LL + c * LC;
    const float* __restrict__ xpp = g_xpt + (size_t)ch * LL + c * LC;
    const float* __restrict__ rp  = g_xdbl + (size_t)(b*LL + c*LC) * XD + DR + n0;
    float* __restrict__ yp = g_yt + (size_t)ch * LL + c * LC;

    float dt[2][4], xv[2][4];
    float2 Bv[2][4], Cv[2][4];

    #pragma unroll
    for (int u = 0; u < 4; ++u) {
        dt[0][u] = __ldg(dtp + u);
        xv[0][u] = __ldg(xpp + u);
        Bv[0][u] = *(const float2*)(rp + (size_t)u * XD);
        Cv[0][u] = *(const float2*)(rp + (size_t)u * XD + DS);
    }

    for (int l = 0; l < LC; l += 8) {
        #pragma unroll
        for (int u = 0; u < 4; ++u) {
            int ll = l + 4 + u;
            dt[1][u] = __ldg(dtp + ll);
            xv[1][u] = __ldg(xpp + ll);
            Bv[1][u] = *(const float2*)(rp + (size_t)ll * XD);
            Cv[1][u] = *(const float2*)(rp + (size_t)ll * XD + DS);
        }
        #pragma unroll
        for (int u = 0; u < 4; ++u) {
            float dtx = dt[0][u] * xv[0][u];
            h0 = fmaf(__expf(dt[0][u] * A0), h0, dtx * Bv[0][u].x);
            h1 = fmaf(__expf(dt[0][u] * A1), h1, dtx * Bv[0][u].y);
            float y = fmaf(h0, Cv[0][u].x, h1 * Cv[0][u].y);
            y += __shfl_down_sync(0xffffffffu, y, 4, 8);
            y += __shfl_down_sync(0xffffffffu, y, 2, 8);
            y += __shfl_down_sync(0xffffffffu, y, 1, 8);
            if (g == 0) yp[l + u] = fmaf(Dd, xv[0][u], y);
        }
        int lp = (l + 8 < LC) ? l + 8 : 0;
        #pragma unroll
        for (int u = 0; u < 4; ++u) {
            int ll = lp + u;
            dt[0][u] = __ldg(dtp + ll);
            xv[0][u] = __ldg(xpp + ll);
            Bv[0][u] = *(const float2*)(rp + (size_t)ll * XD);
            Cv[0][u] = *(const float2*)(rp + (size_t)ll * XD + DS);
        }
        #pragma unroll
        for (int u = 0; u < 4; ++u) {
            float dtx = dt[1][u] * xv[1][u];
            h0 = fmaf(__expf(dt[1][u] * A0), h0, dtx * Bv[1][u].x);
            h1 = fmaf(__expf(dt[1][u] * A1), h1, dtx * Bv[1][u].y);
            float y = fmaf(h0, Cv[1][u].x, h1 * Cv[1][u].y);
            y += __shfl_down_sync(0xffffffffu, y, 4, 8);
            y += __shfl_down_sync(0xffffffffu, y, 2, 8);
            y += __shfl_down_sync(0xffffffffu, y, 1, 8);
            if (g == 0) yp[l + 4 + u] = fmaf(Dd, xv[1][u], y);
        }
    }
}

// ---------------------------------------------------------------------------
// g = y_t * silu(z) -> fp32 into g_delta (feeds int8 quant for out_proj)
// ---------------------------------------------------------------------------
__global__ void gmul_kernel()
{
    __shared__ float sY[32][33];
    const int b = blockIdx.z, d0 = blockIdx.y * 32, l0 = blockIdx.x * 32;
    const int tid = threadIdx.x, tx = tid & 31, ty = tid >> 5;

    #pragma unroll
    for (int i = 0; i < 4; ++i) {
        int dd = ty + i * 8;
        sY[dd][tx] = g_yt[(size_t)(b*DI + d0 + dd) * LL + l0 + tx];
    }
    __syncthreads();
    #pragma unroll
    for (int i = 0; i < 4; ++i) {
        int r = ty + i * 8;
        float z = g_xz[(size_t)(b*LL + l0 + r) * XZW + DI + d0 + tx];
        g_delta[(size_t)(b*LL + l0 + r) * DI + d0 + tx] = sY[tx][r] * siluf(z);
    }
}

// ---------------------------------------------------------------------------
extern "C" void kernel_launch(void* const* d_in, const int* in_sizes, int n_in,
                              void* d_out, int out_size)
{
    const float* x       = (const float*)d_in[0];
    const float* in_proj = (const float*)d_in[1];
    const float* conv_w  = (const float*)d_in[2];
    const float* conv_b  = (const float*)d_in[3];
    const float* x_proj  = (const float*)d_in[4];
    const float* dt_w    = (const float*)d_in[5];
    const float* dt_b    = (const float*)d_in[6];
    const float* A_log   = (const float*)d_in[7];
    const float* Dv      = (const float*)d_in[8];
    const float* out_w   = (const float*)d_in[9];
    float* out = (float*)d_out;

    float *xz, *xpart, *delta;
    __nv_bfloat16 *xphi, *xplo, *w3hi, *w3lo, *dthi, *dtlo, *wdhi, *wdlo;
    int8_t *qx1, *qx2, *qw11, *qw12, *qg1, *qg2, *qw21, *qw22;
    float *scx, *scw1, *scg, *scw2;
    cudaGetSymbolAddress((void**)&xz,    g_xz);
    cudaGetSymbolAddress((void**)&xpart, g_xpart);
    cudaGetSymbolAddress((void**)&delta, g_delta);
    cudaGetSymbolAddress((void**)&xphi,  g_xphi);
    cudaGetSymbolAddress((void**)&xplo,  g_xplo);
    cudaGetSymbolAddress((void**)&w3hi,  g_w3hi);
    cudaGetSymbolAddress((void**)&w3lo,  g_w3lo);
    cudaGetSymbolAddress((void**)&dthi,  g_dthi);
    cudaGetSymbolAddress((void**)&dtlo,  g_dtlo);
    cudaGetSymbolAddress((void**)&wdhi,  g_wdhi);
    cudaGetSymbolAddress((void**)&wdlo,  g_wdlo);
    cudaGetSymbolAddress((void**)&qx1,   g_qx1);
    cudaGetSymbolAddress((void**)&qx2,   g_qx2);
    cudaGetSymbolAddress((void**)&qw11,  g_qw11);
    cudaGetSymbolAddress((void**)&qw12,  g_qw12);
    cudaGetSymbolAddress((void**)&qg1,   g_qg1);
    cudaGetSymbolAddress((void**)&qg2,   g_qg2);
    cudaGetSymbolAddress((void**)&qw21,  g_qw21);
    cudaGetSymbolAddress((void**)&qw22,  g_qw22);
    cudaGetSymbolAddress((void**)&scx,   g_scx);
    cudaGetSymbolAddress((void**)&scw1,  g_scw1);
    cudaGetSymbolAddress((void**)&scg,   g_scg);
    cudaGetSymbolAddress((void**)&scw2,  g_scw2);

    cudaFuncSetAttribute(hmma_gemm, cudaFuncAttributeMaxDynamicSharedMemorySize, HM_SMEM);
    cudaFuncSetAttribute(imma_gemm, cudaFuncAttributeMaxDynamicSharedMemorySize, IM_SMEM);

    // 0-2) int8 split quantization (imma in_proj sits at launch index 3)
    quant_s8<<<NR, 256>>>(x, qx1, qx2, scx, DM);
    quant_s8<<<XZW, 256>>>(in_proj, qw11, qw12, scw1, DM);
    quant_s8<<<DM, 256>>>(out_w, qw21, qw22, scw2, DI);
    // 3) xz = x @ in_proj_w^T  (IMMA split-int8) -> [4096, 4096]
    imma_gemm<<<dim3(XZW/128, NR/64), 128, IM_SMEM>>>(
        qx1, qx2, qw11, qw12, scx, scw1, xz, XZW, DM);
    // 4) conv + silu (bf16 hi/lo + fp32 transposed)
    conv_silu_kernel<<<dim3(LL/32, DI/32, BB), 256>>>(conv_w, conv_b);
    // 5) pad+split x_proj_w; split dt_proj_w
    split_pad_xw<<<(128*DI/4 + 255)/256, 256>>>(x_proj);
    split_bf16<<<(DI*DR/4 + 255)/256, 256>>>(dt_w, wdhi, wdlo, DI*DR/4);
    // 6) x_dbl partials (bf16 HMMA, split-K x8)
    hmma_gemm<<<dim3(1, NR/128, 8), 256, HM_SMEM>>>(
        xphi, xplo, w3hi, w3lo, xpart, 128, DI, DI/8, (size_t)NR*128);
    // 7) reduce partials; bf16-split delta cols
    reduce_xdbl<<<(NR*24 + 255)/256, 256>>>();
    // 8) delta raw (bf16 HMMA)
    hmma_gemm<<<dim3(DI/128, NR/128, 1), 256, HM_SMEM>>>(
        dthi, dtlo, wdhi, wdlo, delta, DI, DR, DR, 0);
    // 9) softplus + transpose
    dtrans_kernel<<<dim3(LL/32, DI/32, BB), 256>>>(dt_b);
    // 10) chunked selective scan (16 chunks of 128)
    scan_pass1<<<dim3((BB*DI)/32, NCH-1), 256>>>(A_log);
    scan_pass2<<<dim3((BB*DI)/32, NCH), 256>>>(A_log, Dv);
    // 11) g = y * silu(z) -> fp32 g_delta
    gmul_kernel<<<dim3(LL/32, DI/32, BB), 256>>>();
    // 12) quantize g
    quant_s8<<<NR, 256>>>(delta, qg1, qg2, scg, DI);
    // 13) out = g @ out_proj_w^T (IMMA split-int8)
    imma_gemm<<<dim3(DM/128, NR/64), 128, IM_SMEM>>>(
        qg1, qg2, qw21, qw22, scg, scw2, out, DM, DI);
}

// round 14
// speedup vs baseline: 1.9081x; 1.9081x over previous
#include <cuda_runtime.h>
#include <cuda_bf16.h>
#include <cstdint>
#include <math.h>

// Problem constants (fixed by reference)
#define BB 2
#define LL 2048
#define DM 1024
#define DI 2048
#define DS 16
#define DR 64
#define NR (BB*LL)     // 4096 rows (b,l)
#define XZW (2*DI)     // 4096
#define XD  96         // dt_rank + 2*d_state
#define NCH 16
#define LC (LL/NCH)    // 128

// Scratch (device globals; no allocation allowed)
__device__ float g_xz  [(size_t)NR*XZW];   // in_proj output [B,L,2*DI]
__device__ float g_xpt [(size_t)BB*DI*LL]; // conv+silu output transposed [B,DI,L]
__device__ float g_xdbl[(size_t)NR*XD];    // x_proj output [B,L,96]
__device__ float g_dtt [(size_t)BB*DI*LL]; // softplus(delta) transposed [B,DI,L]
__device__ float g_yt  [(size_t)BB*DI*LL]; // scan output (+D*x) [B,DI,L]
__device__ float g_xpart[(size_t)8*NR*128];// xproj split-K partials [8][4096][128]
__device__ float g_delta[(size_t)NR*DI];   // raw delta GEMM output [B,L,DI]
__device__ float g_q   [(size_t)(NCH-1)*BB*DI*DS]; // pass1 final states
__device__ float g_sdt [(size_t)(NCH-1)*BB*DI];    // pass1 per-chunk sum(dt)

// bf16 split buffers for tensor-core GEMMs
__device__ __nv_bfloat16 g_xhi [(size_t)NR*DM];
__device__ __nv_bfloat16 g_xlo [(size_t)NR*DM];
__device__ __nv_bfloat16 g_w1hi[(size_t)XZW*DM];
__device__ __nv_bfloat16 g_w1lo[(size_t)XZW*DM];
__device__ __nv_bfloat16 g_xphi[(size_t)NR*DI];   // conv+silu output hi
__device__ __nv_bfloat16 g_xplo[(size_t)NR*DI];   // conv+silu output lo
__device__ __nv_bfloat16 g_w3hi[(size_t)128*DI];  // x_proj_w padded to 128 rows
__device__ __nv_bfloat16 g_w3lo[(size_t)128*DI];
__device__ __nv_bfloat16 g_dthi[(size_t)NR*DR];   // x_dbl[:, :64] hi (delta A)
__device__ __nv_bfloat16 g_dtlo[(size_t)NR*DR];
__device__ __nv_bfloat16 g_wdhi[(size_t)DI*DR];   // dt_proj_w hi/lo
__device__ __nv_bfloat16 g_wdlo[(size_t)DI*DR];
__device__ __nv_bfloat16 g_ghi [(size_t)NR*DI];
__device__ __nv_bfloat16 g_glo [(size_t)NR*DI];
__device__ __nv_bfloat16 g_w2hi[(size_t)DM*DI];
__device__ __nv_bfloat16 g_w2lo[(size_t)DM*DI];

__device__ __forceinline__ float siluf(float x) { return x / (1.0f + __expf(-x)); }
__device__ __forceinline__ float softplusf(float x) {
    return (x > 20.0f) ? x : log1pf(__expf(x));
}

// ===========================================================================
// Base-target (sm_103, no 'a') tensor path: ldmatrix + mma.sync + cp.async
// ===========================================================================
__device__ __forceinline__ uint32_t smem_u32(const void* p) {
    uint32_t a;
    asm("{ .reg .u64 t; cvta.to.shared.u64 t, %1; cvt.u32.u64 %0, t; }" : "=r"(a) : "l"(p));
    return a;
}
__device__ __forceinline__ void cpa16(uint32_t dst, const void* src) {
    asm volatile("cp.async.cg.shared.global [%0], [%1], 16;" :: "r"(dst), "l"(src));
}
__device__ __forceinline__ void ldsm4(uint32_t* r, uint32_t a) {
    asm volatile("ldmatrix.sync.aligned.m8n8.x4.shared.b16 {%0,%1,%2,%3}, [%4];"
                 : "=r"(r[0]), "=r"(r[1]), "=r"(r[2]), "=r"(r[3]) : "r"(a));
}
__device__ __forceinline__ void mma16816(float* c, const uint32_t* a, const uint32_t* b) {
    asm volatile("mma.sync.aligned.m16n8k16.row.col.f32.bf16.bf16.f32 "
                 "{%0,%1,%2,%3}, {%4,%5,%6,%7}, {%8,%9}, {%0,%1,%2,%3};"
                 : "+f"(c[0]), "+f"(c[1]), "+f"(c[2]), "+f"(c[3])
                 : "r"(a[0]), "r"(a[1]), "r"(a[2]), "r"(a[3]), "r"(b[0]), "r"(b[1]));
}

// ===========================================================================
// Split fp32 -> bf16 hi + bf16 lo (residual)
// ===========================================================================
__global__ void split_bf16(const float* __restrict__ in, __nv_bfloat16* __restrict__ hi,
                           __nv_bfloat16* __restrict__ lo, int n4)
{
    int i = blockIdx.x * blockDim.x + threadIdx.x;
    if (i >= n4) return;
    float4 v = *(const float4*)(in + (size_t)i * 4);
    __nv_bfloat16 h0 = __float2bfloat16(v.x), h1 = __float2bfloat16(v.y);
    __nv_bfloat16 h2 = __float2bfloat16(v.z), h3 = __float2bfloat16(v.w);
    __nv_bfloat16 l0 = __float2bfloat16(v.x - __bfloat162float(h0));
    __nv_bfloat16 l1 = __float2bfloat16(v.y - __bfloat162float(h1));
    __nv_bfloat16 l2 = __float2bfloat16(v.z - __bfloat162float(h2));
    __nv_bfloat16 l3 = __float2bfloat16(v.w - __bfloat162float(h3));
    __nv_bfloat162* hp = (__nv_bfloat162*)(hi + (size_t)i * 4);
    __nv_bfloat162* lp = (__nv_bfloat162*)(lo + (size_t)i * 4);
    hp[0] = __nv_bfloat162(h0, h1); hp[1] = __nv_bfloat162(h2, h3);
    lp[0] = __nv_bfloat162(l0, l1); lp[1] = __nv_bfloat162(l2, l3);
}

// Split + zero-pad x_proj_w [96,2048] -> [128,2048] bf16 hi/lo
__global__ void split_pad_xw(const float* __restrict__ xw)
{
    int i = blockIdx.x * blockDim.x + threadIdx.x;   // float4 index over [128][2048]
    if (i >= 128 * DI / 4) return;
    int row = i >> 9;                                // 512 float4 per row
    float4 v = make_float4(0.f, 0.f, 0.f, 0.f);
    if (row < 96) v = *(const float4*)(xw + (size_t)i * 4);
    __nv_bfloat16 h0 = __float2bfloat16(v.x), h1 = __float2bfloat16(v.y);
    __nv_bfloat16 h2 = __float2bfloat16(v.z), h3 = __float2bfloat16(v.w);
    __nv_bfloat162* hp = (__nv_bfloat162*)(g_w3hi + (size_t)i * 4);
    __nv_bfloat162* lp = (__nv_bfloat162*)(g_w3lo + (size_t)i * 4);
    hp[0] = __nv_bfloat162(h0, h1); hp[1] = __nv_bfloat162(h2, h3);
    lp[0] = __nv_bfloat162(__float2bfloat16(v.x - __bfloat162float(h0)),
                           __float2bfloat16(v.y - __bfloat162float(h1)));
    lp[1] = __nv_bfloat162(__float2bfloat16(v.z - __bfloat162float(h2)),
                           __float2bfloat16(v.w - __bfloat162float(h3)));
}

// ===========================================================================
// Split-bf16 HMMA GEMM v5: C[M,N] = A[M,K] @ B[N,K]^T, fp32 accumulate.
// CTA tile 128x128, warp tile 64x32 (8 warps, 2x4), stage K=16.
// packed-32B rows + XOR swizzle, 6-stage cp.async ring, one barrier per
// TWO K-stages (warp drift -> ldsm/MMA overlap), 2 CTAs/SM.
// Split-K via blockIdx.z (kChunk columns each, partial written at z*cStride).
// ===========================================================================
#define OA_LO 4096         // +128*32
#define OB_HI 8192
#define OB_LO 12288
#define STG   16384
#define NSTG  6
#define HM_SMEM (NSTG*STG) // 98304 per CTA -> 2 CTAs/SM

__global__ void __launch_bounds__(256, 2)
hmma_gemm(const __nv_bfloat16* __restrict__ Ahi, const __nv_bfloat16* __restrict__ Alo,
          const __nv_bfloat16* __restrict__ Bhi, const __nv_bfloat16* __restrict__ Blo,
          float* __restrict__ C, int N, int K, int kChunk, size_t cStride)
{
    extern __shared__ char sm_[];
    const uint32_t sb = smem_u32(sm_);
    const int tid = threadIdx.x, lane = tid & 31, wid = tid >> 5;
    const int wm = wid >> 2, wn = wid & 3;
    const int m0 = blockIdx.y * 128, n0 = blockIdx.x * 128;
    const int kOffB = blockIdx.z * kChunk * 2;      // byte offset along K
    C += (size_t)blockIdx.z * cStride;
    const int nst = kChunk >> 4;

    float acc[4][4][4];
    #pragma unroll
    for (int i = 0; i < 4; ++i)
        #pragma unroll
        for (int j = 0; j < 4; ++j)
            #pragma unroll
            for (int q = 0; q < 4; ++q) acc[i][j][q] = 0.0f;

    // cp.async write mapping: row lr, chunk ch; swizzled offset
    const int lr = wid * 16 + (lane & 7) + ((lane >> 4) << 3);
    const int ch = (lane >> 3) & 1;
    const uint32_t wo = (uint32_t)(lr * 32 + ((ch ^ ((lr >> 2) & 1)) << 4));
    const int gh = ch * 16;                          // byte offset in 32B k-slab
    const char* pAh = (const char*)(Ahi + (size_t)(m0 + lr) * K) + kOffB + gh;
    const char* pAl = (const char*)(Alo + (size_t)(m0 + lr) * K) + kOffB + gh;
    const char* pBh = (const char*)(Bhi + (size_t)(n0 + lr) * K) + kOffB + gh;
    const char* pBl = (const char*)(Blo + (size_t)(n0 + lr) * K) + kOffB + gh;

    auto load_stage = [&](int s) {
        if (s < nst) {
            const uint32_t st = sb + (uint32_t)(s % NSTG) * STG;
            const int kb = s * 32;
            cpa16(st + wo, pAh + kb);
            cpa16(st + OA_LO + wo, pAl + kb);
            cpa16(st + OB_HI + wo, pBh + kb);
            cpa16(st + OB_LO + wo, pBl + kb);
        }
        asm volatile("cp.async.commit_group;");
    };

    // prologue: 4 stages in flight
    load_stage(0);
    load_stage(1);
    load_stage(2);
    load_stage(3);

    // ldsm read offsets (swizzle preserved under +16-row steps)
    const int rowA = wm * 64 + (lane & 15);
    const int cA = lane >> 4;
    const uint32_t aOff = (uint32_t)(rowA * 32 + ((cA ^ ((rowA >> 2) & 1)) << 4));
    const int rowB = wn * 32 + (lane & 7) + ((lane >> 4) << 3);
    const int cB = (lane >> 3) & 1;
    const uint32_t bOff = (uint32_t)(rowB * 32 + ((cB ^ ((rowB >> 2) & 1)) << 4));

    auto process_stage = [&](int s) {
        const uint32_t st = sb + (uint32_t)(s % NSTG) * STG;
        const uint32_t aB = st + aOff;
        const uint32_t bB = st + OB_HI + bOff;

        uint32_t ah[4][4], al[4][4], bh[2][4], bl[2][4];
        ldsm4(bh[0], bB);
        ldsm4(bh[1], bB + 512);
        #pragma unroll
        for (int i = 0; i < 4; ++i) ldsm4(ah[i], aB + i * 512);
        #pragma unroll
        for (int i = 0; i < 4; ++i) ldsm4(al[i], aB + OA_LO + i * 512);
        ldsm4(bl[0], bB + (OB_LO - OB_HI));
        ldsm4(bl[1], bB + (OB_LO - OB_HI) + 512);

        #pragma unroll
        for (int i = 0; i < 4; ++i)
            #pragma unroll
            for (int j = 0; j < 4; ++j)
                mma16816(acc[i][j], ah[i], &bh[j >> 1][(j & 1) * 2]);
        #pragma unroll
        for (int i = 0; i < 4; ++i)
            #pragma unroll
            for (int j = 0; j < 4; ++j)
                mma16816(acc[i][j], al[i], &bh[j >> 1][(j & 1) * 2]);
        #pragma unroll
        for (int i = 0; i < 4; ++i)
            #pragma unroll
            for (int j = 0; j < 4; ++j)
                mma16816(acc[i][j], ah[i], &bl[j >> 1][(j & 1) * 2]);
    };

    for (int p = 0; p < (nst >> 1); ++p) {
        asm volatile("cp.async.wait_group 2;");
        __syncthreads();
        load_stage(2*p + 4);
        load_stage(2*p + 5);
        process_stage(2*p);
        process_stage(2*p + 1);
    }

    // epilogue: fp32 direct to global
    #pragma unroll
    for (int i = 0; i < 4; ++i)
        #pragma unroll
        for (int j = 0; j < 4; ++j) {
            int row = m0 + wm*64 + i*16 + (lane >> 2);
            int col = n0 + wn*32 + j*8 + (lane & 3)*2;
            *(float2*)(C + (size_t)row * N + col) =
                make_float2(acc[i][j][0], acc[i][j][1]);
            *(float2*)(C + (size_t)(row + 8) * N + col) =
                make_float2(acc[i][j][2], acc[i][j][3]);
        }
}

// Reduce xproj split-K partials: g_xdbl[m][c] = sum_z g_xpart[z][m][c], c<96.
// Also emits bf16 hi/lo of cols 0..63 (delta GEMM A operand).
__global__ void reduce_xdbl()
{
    int idx = blockIdx.x * blockDim.x + threadIdx.x;   // 0 .. 4096*24-1
    if (idx >= NR * 24) return;
    int m = idx / 24, c = (idx % 24) * 4;
    const float* p = g_xpart + (size_t)m * 128 + c;
    float4 s = make_float4(0.f, 0.f, 0.f, 0.f);
    #pragma unroll
    for (int z = 0; z < 8; ++z) {
        float4 v = *(const float4*)(p + (size_t)z * NR * 128);
        s.x += v.x; s.y += v.y; s.z += v.z; s.w += v.w;
    }
    *(float4*)(g_xdbl + (size_t)m * XD + c) = s;
    if (c < DR) {
        __nv_bfloat16 h0 = __float2bfloat16(s.x), h1 = __float2bfloat16(s.y);
        __nv_bfloat16 h2 = __float2bfloat16(s.z), h3 = __float2bfloat16(s.w);
        __nv_bfloat162* hp = (__nv_bfloat162*)(g_dthi + (size_t)m * DR + c);
        __nv_bfloat162* lp = (__nv_bfloat162*)(g_dtlo + (size_t)m * DR + c);
        hp[0] = __nv_bfloat162(h0, h1); hp[1] = __nv_bfloat162(h2, h3);
        lp[0] = __nv_bfloat162(__float2bfloat16(s.x - __bfloat162float(h0)),
                               __float2bfloat16(s.y - __bfloat162float(h1)));
        lp[1] = __nv_bfloat162(__float2bfloat16(s.z - __bfloat162float(h2)),
                               __float2bfloat16(s.w - __bfloat162float(h3)));
    }
}

// ---------------------------------------------------------------------------
// Causal depthwise conv (width 4) + bias + silu over xz[:, :, 0:DI].
// Writes bf16 hi/lo [B,L,DI] (for xproj HMMA) and fp32 transposed [B,DI,L].
// ---------------------------------------------------------------------------
__global__ void conv_silu_kernel(const float* __restrict__ conv_w,
                                 const float* __restrict__ conv_b)
{
    __shared__ float sIn[35][33];
    __shared__ float sOut[32][33];
    const int b = blockIdx.z, d0 = blockIdx.y * 32, l0 = blockIdx.x * 32;
    const int tid = threadIdx.x, tx = tid & 31, ty = tid >> 5;

    for (int r = ty; r < 35; r += 8) {
        int gl = l0 + r - 3;
        sIn[r][tx] = (gl >= 0) ? g_xz[(size_t)(b*LL + gl) * XZW + d0 + tx] : 0.0f;
    }
    __syncthreads();

    float4 w = *(const float4*)(conv_w + (d0 + tx) * 4);
    float cb = conv_b[d0 + tx];
    #pragma unroll
    for (int i = 0; i < 4; ++i) {
        int r = ty + i * 8;
        float v = sIn[r][tx]*w.x + sIn[r+1][tx]*w.y + sIn[r+2][tx]*w.z + sIn[r+3][tx]*w.w + cb;
        v = siluf(v);
        sOut[r][tx] = v;
        size_t idx = (size_t)(b*LL + l0 + r) * DI + d0 + tx;
        __nv_bfloat16 h = __float2bfloat16(v);
        g_xphi[idx] = h;
        g_xplo[idx] = __float2bfloat16(v - __bfloat162float(h));
    }
    __syncthreads();
    #pragma unroll
    for (int i = 0; i < 4; ++i) {
        int dd = ty + i * 8;
        g_xpt[(size_t)(b*DI + d0 + dd) * LL + l0 + tx] = sOut[tx][dd];
    }
}

// ---------------------------------------------------------------------------
// delta transpose + bias + softplus:
// g_dtt[(b*DI+n)*LL + l] = softplus(g_delta[(b*LL+l)*DI + n] + dtb[n])
// ---------------------------------------------------------------------------
__global__ void dtrans_kernel(const float* __restrict__ dtb)
{
    __shared__ float sD[32][33];
    const int b = blockIdx.z, n0 = blockIdx.y * 32, l0 = blockIdx.x * 32;
    const int tid = threadIdx.x, tx = tid & 31, ty = tid >> 5;

    #pragma unroll
    for (int i = 0; i < 4; ++i) {
        int r = ty + i * 8;   // local l
        sD[r][tx] = g_delta[(size_t)(b*LL + l0 + r) * DI + n0 + tx];
    }
    __syncthreads();
    #pragma unroll
    for (int i = 0; i < 4; ++i) {
        int ny = ty + i * 8;  // local n
        int n = n0 + ny;
        float v = softplusf(sD[tx][ny] + dtb[n]);
        g_dtt[(size_t)(b*DI + n) * LL + l0 + tx] = v;
    }
}

// ---------------------------------------------------------------------------
// Chunked selective scan, pass 1: per-chunk final state q_c and sum(dt).
// Thread = (channel, 2 states), 8 lanes per channel. Chunks 0..NCH-2.
// ---------------------------------------------------------------------------
__global__ __launch_bounds__(256)
void scan_pass1(const float* __restrict__ A_log)
{
    const int tid = threadIdx.x;
    const int ch = blockIdx.x * 32 + (tid >> 3);
    const int g  = tid & 7;
    const int c  = blockIdx.y;            // 0..NCH-2
    const int d  = ch & (DI - 1);
    const int b  = ch >> 11;
    const int n0 = g * 2;

    const float A0 = -__expf(A_log[d*DS + n0]);
    const float A1 = -__expf(A_log[d*DS + n0 + 1]);

    const float* __restrict__ dtp = g_dtt + (size_t)ch * LL + c * LC;
    const float* __restrict__ xpp = g_xpt + (size_t)ch * LL + c * LC;
    const float* __restrict__ rp  = g_xdbl + (size_t)(b*LL + c*LC) * XD + DR + n0;

    float h0 = 0.f, h1 = 0.f, sdt = 0.f;
    float dt[2][4], xv[2][4];
    float2 Bv[2][4];

    #pragma unroll
    for (int u = 0; u < 4; ++u) {
        dt[0][u] = __ldg(dtp + u);
        xv[0][u] = __ldg(xpp + u);
        Bv[0][u] = *(const float2*)(rp + (size_t)u * XD);
    }

    for (int l = 0; l < LC; l += 8) {
        #pragma unroll
        for (int u = 0; u < 4; ++u) {
            int ll = l + 4 + u;
            dt[1][u] = __ldg(dtp + ll);
            xv[1][u] = __ldg(xpp + ll);
            Bv[1][u] = *(const float2*)(rp + (size_t)ll * XD);
        }
        #pragma unroll
        for (int u = 0; u < 4; ++u) {
            float dtx = dt[0][u] * xv[0][u];
            h0 = fmaf(__expf(dt[0][u] * A0), h0, dtx * Bv[0][u].x);
            h1 = fmaf(__expf(dt[0][u] * A1), h1, dtx * Bv[0][u].y);
            sdt += dt[0][u];
        }
        int lp = (l + 8 < LC) ? l + 8 : 0;    // clamped prefetch (last unused)
        #pragma unroll
        for (int u = 0; u < 4; ++u) {
            int ll = lp + u;
            dt[0][u] = __ldg(dtp + ll);
            xv[0][u] = __ldg(xpp + ll);
            Bv[0][u] = *(const float2*)(rp + (size_t)ll * XD);
        }
        #pragma unroll
        for (int u = 0; u < 4; ++u) {
            float dtx = dt[1][u] * xv[1][u];
            h0 = fmaf(__expf(dt[1][u] * A0), h0, dtx * Bv[1][u].x);
            h1 = fmaf(__expf(dt[1][u] * A1), h1, dtx * Bv[1][u].y);
            sdt += dt[1][u];
        }
    }

    float* qp = g_q + ((size_t)c * (BB*DI) + ch) * DS + n0;
    qp[0] = h0; qp[1] = h1;
    if (g == 0) g_sdt[(size_t)c * (BB*DI) + ch] = sdt;
}

// ---------------------------------------------------------------------------
// Chunked selective scan, pass 2: carry-in from pass1, full y output.
// ---------------------------------------------------------------------------
__global__ __launch_bounds__(256)
void scan_pass2(const float* __restrict__ A_log, const float* __restrict__ Dv)
{
    const int tid = threadIdx.x;
    const int ch = blockIdx.x * 32 + (tid >> 3);
    const int g  = tid & 7;
    const int c  = blockIdx.y;            // 0..NCH-1
    const int d  = ch & (DI - 1);
    const int b  = ch >> 11;
    const int n0 = g * 2;

    const float A0 = -__expf(A_log[d*DS + n0]);
    const float A1 = -__expf(A_log[d*DS + n0 + 1]);
    const float Dd = Dv[d];

    float h0 = 0.f, h1 = 0.f;
    for (int j = 0; j < c; ++j) {
        float s = __ldg(g_sdt + (size_t)j * (BB*DI) + ch);
        const float* qp = g_q + ((size_t)j * (BB*DI) + ch) * DS + n0;
        h0 = fmaf(__expf(s * A0), h0, __ldg(qp));
        h1 = fmaf(__expf(s * A1), h1, __ldg(qp + 1));
    }

    const float* __restrict__ dtp = g_dtt + (size_t)ch * LL + c * LC;
    const float* __restrict__ xpp = g_xpt + (size_t)ch * LL + c * LC;
    const float* __restrict__ rp  = g_xdbl + (size_t)(b*LL + c*LC) * XD + DR + n0;
    float* __restrict__ yp = g_yt + (size_t)ch * LL + c * LC;

    float dt[2][4], xv[2][4];
    float2 Bv[2][4], Cv[2][4];

    #pragma unroll
    for (int u = 0; u < 4; ++u) {
        dt[0][u] = __ldg(dtp + u);
        xv[0][u] = __ldg(xpp + u);
        Bv[0][u] = *(const float2*)(rp + (size_t)u * XD);
        Cv[0][u] = *(const float2*)(rp + (size_t)u * XD + DS);
    }

    for (int l = 0; l < LC; l += 8) {
        #pragma unroll
        for (int u = 0; u < 4; ++u) {
            int ll = l + 4 + u;
            dt[1][u] = __ldg(dtp + ll);
            xv[1][u] = __ldg(xpp + ll);
            Bv[1][u] = *(const float2*)(rp + (size_t)ll * XD);
            Cv[1][u] = *(const float2*)(rp + (size_t)ll * XD + DS);
        }
        #pragma unroll
        for (int u = 0; u < 4; ++u) {
            float dtx = dt[0][u] * xv[0][u];
            h0 = fmaf(__expf(dt[0][u] * A0), h0, dtx * Bv[0][u].x);
            h1 = fmaf(__expf(dt[0][u] * A1), h1, dtx * Bv[0][u].y);
            float y = fmaf(h0, Cv[0][u].x, h1 * Cv[0][u].y);
            y += __shfl_down_sync(0xffffffffu, y, 4, 8);
            y += __shfl_down_sync(0xffffffffu, y, 2, 8);
            y += __shfl_down_sync(0xffffffffu, y, 1, 8);
            if (g == 0) yp[l + u] = fmaf(Dd, xv[0][u], y);
        }
        int lp = (l + 8 < LC) ? l + 8 : 0;
        #pragma unroll
        for (int u = 0; u < 4; ++u) {
            int ll = lp + u;
            dt[0][u] = __ldg(dtp + ll);
            xv[0][u] = __ldg(xpp + ll);
            Bv[0][u] = *(const float2*)(rp + (size_t)ll * XD);
            Cv[0][u] = *(const float2*)(rp + (size_t)ll * XD + DS);
        }
        #pragma unroll
        for (int u = 0; u < 4; ++u) {
            float dtx = dt[1][u] * xv[1][u];
            h0 = fmaf(__expf(dt[1][u] * A0), h0, dtx * Bv[1][u].x);
            h1 = fmaf(__expf(dt[1][u] * A1), h1, dtx * Bv[1][u].y);
            float y = fmaf(h0, Cv[1][u].x, h1 * Cv[1][u].y);
            y += __shfl_down_sync(0xffffffffu, y, 4, 8);
            y += __shfl_down_sync(0xffffffffu, y, 2, 8);
            y += __shfl_down_sync(0xffffffffu, y, 1, 8);
            if (g == 0) yp[l + 4 + u] = fmaf(Dd, xv[1][u], y);
        }
    }
}

// ---------------------------------------------------------------------------
// g = y_t * silu(z), fused with bf16 hi/lo split (feeds out_proj HMMA)
// ---------------------------------------------------------------------------
__global__ void gmul_split_kernel()
{
    __shared__ float sY[32][33];
    const int b = blockIdx.z, d0 = blockIdx.y * 32, l0 = blockIdx.x * 32;
    const int tid = threadIdx.x, tx = tid & 31, ty = tid >> 5;

    #pragma unroll
    for (int i = 0; i < 4; ++i) {
        int dd = ty + i * 8;
        sY[dd][tx] = g_yt[(size_t)(b*DI + d0 + dd) * LL + l0 + tx];
    }
    __syncthreads();
    #pragma unroll
    for (int i = 0; i < 4; ++i) {
        int r = ty + i * 8;
        size_t idx = (size_t)(b*LL + l0 + r) * DI + d0 + tx;
        float z = g_xz[(size_t)(b*LL + l0 + r) * XZW + DI + d0 + tx];
        float v = sY[tx][r] * siluf(z);
        __nv_bfloat16 h = __float2bfloat16(v);
        g_ghi[idx] = h;
        g_glo[idx] = __float2bfloat16(v - __bfloat162float(h));
    }
}

// ---------------------------------------------------------------------------
extern "C" void kernel_launch(void* const* d_in, const int* in_sizes, int n_in,
                              void* d_out, int out_size)
{
    const float* x       = (const float*)d_in[0];
    const float* in_proj = (const float*)d_in[1];
    const float* conv_w  = (const float*)d_in[2];
    const float* conv_b  = (const float*)d_in[3];
    const float* x_proj  = (const float*)d_in[4];
    const float* dt_w    = (const float*)d_in[5];
    const float* dt_b    = (const float*)d_in[6];
    const float* A_log   = (const float*)d_in[7];
    const float* Dv      = (const float*)d_in[8];
    const float* out_w   = (const float*)d_in[9];
    float* out = (float*)d_out;

    float *xz, *xpart, *delta;
    __nv_bfloat16 *xhi, *xlo, *w1hi, *w1lo, *xphi, *xplo, *w3hi, *w3lo;
    __nv_bfloat16 *dthi, *dtlo, *wdhi, *wdlo, *ghi, *glo, *w2hi, *w2lo;
    cudaGetSymbolAddress((void**)&xz,    g_xz);
    cudaGetSymbolAddress((void**)&xpart, g_xpart);
    cudaGetSymbolAddress((void**)&delta, g_delta);
    cudaGetSymbolAddress((void**)&xhi,   g_xhi);
    cudaGetSymbolAddress((void**)&xlo,   g_xlo);
    cudaGetSymbolAddress((void**)&w1hi,  g_w1hi);
    cudaGetSymbolAddress((void**)&w1lo,  g_w1lo);
    cudaGetSymbolAddress((void**)&xphi,  g_xphi);
    cudaGetSymbolAddress((void**)&xplo,  g_xplo);
    cudaGetSymbolAddress((void**)&w3hi,  g_w3hi);
    cudaGetSymbolAddress((void**)&w3lo,  g_w3lo);
    cudaGetSymbolAddress((void**)&dthi,  g_dthi);
    cudaGetSymbolAddress((void**)&dtlo,  g_dtlo);
    cudaGetSymbolAddress((void**)&wdhi,  g_wdhi);
    cudaGetSymbolAddress((void**)&wdlo,  g_wdlo);
    cudaGetSymbolAddress((void**)&ghi,   g_ghi);
    cudaGetSymbolAddress((void**)&glo,   g_glo);
    cudaGetSymbolAddress((void**)&w2hi,  g_w2hi);
    cudaGetSymbolAddress((void**)&w2lo,  g_w2lo);

    cudaFuncSetAttribute(hmma_gemm, cudaFuncAttributeMaxDynamicSharedMemorySize, HM_SMEM);

    // 0-2) splits (so in_proj hmma sits at launch index 3 for ncu)
    split_bf16<<<(NR*DM/4 + 255)/256, 256>>>(x, xhi, xlo, NR*DM/4);
    split_bf16<<<(XZW*DM/4 + 255)/256, 256>>>(in_proj, w1hi, w1lo, XZW*DM/4);
    split_bf16<<<(DM*DI/4 + 255)/256, 256>>>(out_w, w2hi, w2lo, DM*DI/4);
    // 3) xz = x @ in_proj_w^T  -> [4096, 4096]
    hmma_gemm<<<dim3(XZW/128, NR/128, 1), 256, HM_SMEM>>>(
        xhi, xlo, w1hi, w1lo, xz, XZW, DM, DM, 0);
    // 4) conv + silu (writes bf16 hi/lo + fp32 transposed)
    conv_silu_kernel<<<dim3(LL/32, DI/32, BB), 256>>>(conv_w, conv_b);
    // 5) pad+split x_proj_w; split dt_proj_w
    split_pad_xw<<<(128*DI/4 + 255)/256, 256>>>(x_proj);
    split_bf16<<<(DI*DR/4 + 255)/256, 256>>>(dt_w, wdhi, wdlo, DI*DR/4);
    // 6) x_dbl partials = x_p @ x_proj_w^T (split-K over 8 chunks of 256)
    hmma_gemm<<<dim3(1, NR/128, 8), 256, HM_SMEM>>>(
        xphi, xplo, w3hi, w3lo, xpart, 128, DI, DI/8, (size_t)NR*128);
    // 7) reduce partials -> g_xdbl; also bf16-split delta cols
    reduce_xdbl<<<(NR*24 + 255)/256, 256>>>();
    // 8) delta raw = x_dbl[:, :64] @ dt_proj_w^T (HMMA) -> [4096, 2048]
    hmma_gemm<<<dim3(DI/128, NR/128, 1), 256, HM_SMEM>>>(
        dthi, dtlo, wdhi, wdlo, delta, DI, DR, DR, 0);
    // 9) softplus(delta + bias), transposed to [B,DI,L]
    dtrans_kernel<<<dim3(LL/32, DI/32, BB), 256>>>(dt_b);
    // 10) chunked selective scan (2 passes, 16 chunks of 128)
    scan_pass1<<<dim3((BB*DI)/32, NCH-1), 256>>>(A_log);
    scan_pass2<<<dim3((BB*DI)/32, NCH), 256>>>(A_log, Dv);
    // 11) g = y * silu(z) fused with bf16 split
    gmul_split_kernel<<<dim3(LL/32, DI/32, BB), 256>>>();
    // 12) out = g @ out_proj_w^T
    hmma_gemm<<<dim3(DM/128, NR/128, 1), 256, HM_SMEM>>>(
        ghi, glo, w2hi, w2lo, out, DM, DI, DI, 0);
}

// round 15
// speedup vs baseline: 2.3381x; 1.2253x over previous
#include <cuda_runtime.h>
#include <cuda_bf16.h>
#include <cuda_fp16.h>
#include <cstdint>
#include <math.h>

// Problem constants (fixed by reference)
#define BB 2
#define LL 2048
#define DM 1024
#define DI 2048
#define DS 16
#define DR 64
#define NR (BB*LL)     // 4096 rows (b,l)
#define XZW (2*DI)     // 4096
#define XD  96         // dt_rank + 2*d_state
#define NCH 16
#define LC (LL/NCH)    // 128

// Scratch (device globals; no allocation allowed)
__device__ float g_xz  [(size_t)NR*XZW];   // in_proj output [B,L,2*DI]
__device__ float g_xpt [(size_t)BB*DI*LL]; // conv+silu output transposed [B,DI,L]
__device__ float g_xdbl[(size_t)NR*XD];    // x_proj output [B,L,96]
__device__ float g_dtt [(size_t)BB*DI*LL]; // softplus(delta) transposed [B,DI,L]
__device__ float g_yt  [(size_t)BB*DI*LL]; // scan output (+D*x) [B,DI,L]
__device__ float g_xpart[(size_t)8*NR*128];// xproj split-K partials [8][4096][128]
__device__ float g_delta[(size_t)NR*DI];   // raw delta GEMM output [B,L,DI]
__device__ float g_q   [(size_t)(NCH-1)*BB*DI*DS]; // pass1 final states
__device__ float g_sdt [(size_t)(NCH-1)*BB*DI];    // pass1 per-chunk sum(dt)

// bf16 split buffers (xproj + delta GEMMs, 3-pass HMMA)
__device__ __nv_bfloat16 g_xphi[(size_t)NR*DI];   // conv+silu output hi
__device__ __nv_bfloat16 g_xplo[(size_t)NR*DI];   // conv+silu output lo
__device__ __nv_bfloat16 g_w3hi[(size_t)128*DI];  // x_proj_w padded to 128 rows
__device__ __nv_bfloat16 g_w3lo[(size_t)128*DI];
__device__ __nv_bfloat16 g_dthi[(size_t)NR*DR];   // x_dbl[:, :64] hi (delta A)
__device__ __nv_bfloat16 g_dtlo[(size_t)NR*DR];
__device__ __nv_bfloat16 g_wdhi[(size_t)DI*DR];   // dt_proj_w hi/lo
__device__ __nv_bfloat16 g_wdlo[(size_t)DI*DR];

// fp16 buffers (in_proj + out_proj GEMMs, 2-pass HMMA: A single, B split)
__device__ __half g_xh [(size_t)NR*DM];    // x fp16
__device__ __half g_w1h[(size_t)XZW*DM];   // in_proj_w hi
__device__ __half g_w1l[(size_t)XZW*DM];   // in_proj_w lo
__device__ __half g_gh [(size_t)NR*DI];    // g fp16
__device__ __half g_w2h[(size_t)DM*DI];    // out_proj_w hi
__device__ __half g_w2l[(size_t)DM*DI];    // out_proj_w lo

__device__ __forceinline__ float siluf(float x) { return x / (1.0f + __expf(-x)); }
__device__ __forceinline__ float softplusf(float x) {
    return (x > 20.0f) ? x : log1pf(__expf(x));
}

// ===========================================================================
// Base-target (sm_103, no 'a') tensor path: ldmatrix + mma.sync + cp.async
// ===========================================================================
__device__ __forceinline__ uint32_t smem_u32(const void* p) {
    uint32_t a;
    asm("{ .reg .u64 t; cvta.to.shared.u64 t, %1; cvt.u32.u64 %0, t; }" : "=r"(a) : "l"(p));
    return a;
}
__device__ __forceinline__ void cpa16(uint32_t dst, const void* src) {
    asm volatile("cp.async.cg.shared.global [%0], [%1], 16;" :: "r"(dst), "l"(src));
}
__device__ __forceinline__ void ldsm4(uint32_t* r, uint32_t a) {
    asm volatile("ldmatrix.sync.aligned.m8n8.x4.shared.b16 {%0,%1,%2,%3}, [%4];"
                 : "=r"(r[0]), "=r"(r[1]), "=r"(r[2]), "=r"(r[3]) : "r"(a));
}
__device__ __forceinline__ void mma16816(float* c, const uint32_t* a, const uint32_t* b) {
    asm volatile("mma.sync.aligned.m16n8k16.row.col.f32.bf16.bf16.f32 "
                 "{%0,%1,%2,%3}, {%4,%5,%6,%7}, {%8,%9}, {%0,%1,%2,%3};"
                 : "+f"(c[0]), "+f"(c[1]), "+f"(c[2]), "+f"(c[3])
                 : "r"(a[0]), "r"(a[1]), "r"(a[2]), "r"(a[3]), "r"(b[0]), "r"(b[1]));
}
__device__ __forceinline__ void mmaf16(float* c, const uint32_t* a, const uint32_t* b) {
    asm volatile("mma.sync.aligned.m16n8k16.row.col.f32.f16.f16.f32 "
                 "{%0,%1,%2,%3}, {%4,%5,%6,%7}, {%8,%9}, {%0,%1,%2,%3};"
                 : "+f"(c[0]), "+f"(c[1]), "+f"(c[2]), "+f"(c[3])
                 : "r"(a[0]), "r"(a[1]), "r"(a[2]), "r"(a[3]), "r"(b[0]), "r"(b[1]));
}

// ===========================================================================
// fp32 -> fp16 single cast (A operands of 2-pass GEMMs)
// ===========================================================================
__global__ void cast_f16(const float* __restrict__ in, __half* __restrict__ out, int n4)
{
    int i = blockIdx.x * blockDim.x + threadIdx.x;
    if (i >= n4) return;
    float4 v = *(const float4*)(in + (size_t)i * 4);
    __half2* op = (__half2*)(out + (size_t)i * 4);
    op[0] = __floats2half2_rn(v.x, v.y);
    op[1] = __floats2half2_rn(v.z, v.w);
}

// fp32 -> fp16 hi + fp16 lo (residual) — B operands of 2-pass GEMMs
__global__ void split_f16(const float* __restrict__ in, __half* __restrict__ hi,
                          __half* __restrict__ lo, int n4)
{
    int i = blockIdx.x * blockDim.x + threadIdx.x;
    if (i >= n4) return;
    float4 v = *(const float4*)(in + (size_t)i * 4);
    __half h0 = __float2half_rn(v.x), h1 = __float2half_rn(v.y);
    __half h2 = __float2half_rn(v.z), h3 = __float2half_rn(v.w);
    __half2* hp = (__half2*)(hi + (size_t)i * 4);
    __half2* lp = (__half2*)(lo + (size_t)i * 4);
    hp[0] = __half2(h0, h1); hp[1] = __half2(h2, h3);
    lp[0] = __floats2half2_rn(v.x - __half2float(h0), v.y - __half2float(h1));
    lp[1] = __floats2half2_rn(v.z - __half2float(h2), v.w - __half2float(h3));
}

// fp32 -> bf16 hi + bf16 lo (dt_proj_w, 3-pass path)
__global__ void split_bf16(const float* __restrict__ in, __nv_bfloat16* __restrict__ hi,
                           __nv_bfloat16* __restrict__ lo, int n4)
{
    int i = blockIdx.x * blockDim.x + threadIdx.x;
    if (i >= n4) return;
    float4 v = *(const float4*)(in + (size_t)i * 4);
    __nv_bfloat16 h0 = __float2bfloat16(v.x), h1 = __float2bfloat16(v.y);
    __nv_bfloat16 h2 = __float2bfloat16(v.z), h3 = __float2bfloat16(v.w);
    __nv_bfloat162* hp = (__nv_bfloat162*)(hi + (size_t)i * 4);
    __nv_bfloat162* lp = (__nv_bfloat162*)(lo + (size_t)i * 4);
    hp[0] = __nv_bfloat162(h0, h1); hp[1] = __nv_bfloat162(h2, h3);
    lp[0] = __nv_bfloat162(__float2bfloat16(v.x - __bfloat162float(h0)),
                           __float2bfloat16(v.y - __bfloat162float(h1)));
    lp[1] = __nv_bfloat162(__float2bfloat16(v.z - __bfloat162float(h2)),
                           __float2bfloat16(v.w - __bfloat162float(h3)));
}

// Split + zero-pad x_proj_w [96,2048] -> [128,2048] bf16 hi/lo
__global__ void split_pad_xw(const float* __restrict__ xw)
{
    int i = blockIdx.x * blockDim.x + threadIdx.x;
    if (i >= 128 * DI / 4) return;
    int row = i >> 9;
    float4 v = make_float4(0.f, 0.f, 0.f, 0.f);
    if (row < 96) v = *(const float4*)(xw + (size_t)i * 4);
    __nv_bfloat16 h0 = __float2bfloat16(v.x), h1 = __float2bfloat16(v.y);
    __nv_bfloat16 h2 = __float2bfloat16(v.z), h3 = __float2bfloat16(v.w);
    __nv_bfloat162* hp = (__nv_bfloat162*)(g_w3hi + (size_t)i * 4);
    __nv_bfloat162* lp = (__nv_bfloat162*)(g_w3lo + (size_t)i * 4);
    hp[0] = __nv_bfloat162(h0, h1); hp[1] = __nv_bfloat162(h2, h3);
    lp[0] = __nv_bfloat162(__float2bfloat16(v.x - __bfloat162float(h0)),
                           __float2bfloat16(v.y - __bfloat162float(h1)));
    lp[1] = __nv_bfloat162(__float2bfloat16(v.z - __bfloat162float(h2)),
                           __float2bfloat16(v.w - __bfloat162float(h3)));
}

// ===========================================================================
// 2-pass fp16 HMMA GEMM v6: C = A @ (Bhi + Blo)^T, fp32 accumulate.
// A single fp16, B split fp16 hi/lo. CTA 128x128, warp tile 64x32 (8 warps).
// Stage K=16 = 12KB (A 4K + Bhi 4K + Blo 4K); 8-deep cp.async ring,
// barrier per two stages (wait_group 4), packed-32B rows + XOR swizzle.
// 2 CTAs/SM (96KB smem each).
// ===========================================================================
#define F_BH 4096
#define F_BL 8192
#define F_STG 12288
#define F_NSTG 8
#define H2_SMEM (F_NSTG*F_STG)  // 98304

__global__ void __launch_bounds__(256, 2)
hmma2_gemm(const __half* __restrict__ A, const __half* __restrict__ Bhi,
           const __half* __restrict__ Blo, float* __restrict__ C, int N, int K)
{
    extern __shared__ char sm2_[];
    const uint32_t sb = smem_u32(sm2_);
    const int tid = threadIdx.x, lane = tid & 31, wid = tid >> 5;
    const int wm = wid >> 2, wn = wid & 3;
    const int m0 = blockIdx.y * 128, n0 = blockIdx.x * 128;
    const int nst = K >> 4;

    float acc[4][4][4];
    #pragma unroll
    for (int i = 0; i < 4; ++i)
        #pragma unroll
        for (int j = 0; j < 4; ++j)
            #pragma unroll
            for (int q = 0; q < 4; ++q) acc[i][j][q] = 0.0f;

    const int lr = wid * 16 + (lane & 7) + ((lane >> 4) << 3);
    const int ch = (lane >> 3) & 1;
    const uint32_t wo = (uint32_t)(lr * 32 + ((ch ^ ((lr >> 2) & 1)) << 4));
    const int gh = ch * 16;
    const char* pA  = (const char*)(A   + (size_t)(m0 + lr) * K) + gh;
    const char* pBh = (const char*)(Bhi + (size_t)(n0 + lr) * K) + gh;
    const char* pBl = (const char*)(Blo + (size_t)(n0 + lr) * K) + gh;

    auto load_stage = [&](int s) {
        if (s < nst) {
            const uint32_t st = sb + (uint32_t)(s % F_NSTG) * F_STG;
            const int kb = s * 32;
            cpa16(st + wo, pA + kb);
            cpa16(st + F_BH + wo, pBh + kb);
            cpa16(st + F_BL + wo, pBl + kb);
        }
        asm volatile("cp.async.commit_group;");
    };

    // prologue: 6 stages in flight
    load_stage(0); load_stage(1); load_stage(2);
    load_stage(3); load_stage(4); load_stage(5);

    const int rowA = wm * 64 + (lane & 15);
    const int cA = lane >> 4;
    const uint32_t aOff = (uint32_t)(rowA * 32 + ((cA ^ ((rowA >> 2) & 1)) << 4));
    const int rowB = wn * 32 + (lane & 7) + ((lane >> 4) << 3);
    const int cB = (lane >> 3) & 1;
    const uint32_t bOff = (uint32_t)(rowB * 32 + ((cB ^ ((rowB >> 2) & 1)) << 4));

    auto process_stage = [&](int s) {
        const uint32_t st = sb + (uint32_t)(s % F_NSTG) * F_STG;
        const uint32_t aB = st + aOff;
        const uint32_t bB = st + F_BH + bOff;

        uint32_t ah[4][4], bh[2][4], bl[2][4];
        ldsm4(bh[0], bB);
        ldsm4(bh[1], bB + 512);
        #pragma unroll
        for (int i = 0; i < 4; ++i) ldsm4(ah[i], aB + i * 512);
        ldsm4(bl[0], bB + (F_BL - F_BH));
        ldsm4(bl[1], bB + (F_BL - F_BH) + 512);

        #pragma unroll
        for (int i = 0; i < 4; ++i)
            #pragma unroll
            for (int j = 0; j < 4; ++j)
                mmaf16(acc[i][j], ah[i], &bh[j >> 1][(j & 1) * 2]);
        #pragma unroll
        for (int i = 0; i < 4; ++i)
            #pragma unroll
            for (int j = 0; j < 4; ++j)
                mmaf16(acc[i][j], ah[i], &bl[j >> 1][(j & 1) * 2]);
    };

    for (int p = 0; p < (nst >> 1); ++p) {
        asm volatile("cp.async.wait_group 4;");
        __syncthreads();
        load_stage(2*p + 6);
        load_stage(2*p + 7);
        process_stage(2*p);
        process_stage(2*p + 1);
    }

    #pragma unroll
    for (int i = 0; i < 4; ++i)
        #pragma unroll
        for (int j = 0; j < 4; ++j) {
            int row = m0 + wm*64 + i*16 + (lane >> 2);
            int col = n0 + wn*32 + j*8 + (lane & 3)*2;
            *(float2*)(C + (size_t)row * N + col) =
                make_float2(acc[i][j][0], acc[i][j][1]);
            *(float2*)(C + (size_t)(row + 8) * N + col) =
                make_float2(acc[i][j][2], acc[i][j][3]);
        }
}

// ===========================================================================
// Split-bf16 HMMA GEMM v5 (3-pass; xproj + delta), unchanged.
// ===========================================================================
#define OA_LO 4096
#define OB_HI 8192
#define OB_LO 12288
#define STG   16384
#define NSTG  6
#define HM_SMEM (NSTG*STG)

__global__ void __launch_bounds__(256, 2)
hmma_gemm(const __nv_bfloat16* __restrict__ Ahi, const __nv_bfloat16* __restrict__ Alo,
          const __nv_bfloat16* __restrict__ Bhi, const __nv_bfloat16* __restrict__ Blo,
          float* __restrict__ C, int N, int K, int kChunk, size_t cStride)
{
    extern __shared__ char sm_[];
    const uint32_t sb = smem_u32(sm_);
    const int tid = threadIdx.x, lane = tid & 31, wid = tid >> 5;
    const int wm = wid >> 2, wn = wid & 3;
    const int m0 = blockIdx.y * 128, n0 = blockIdx.x * 128;
    const int kOffB = blockIdx.z * kChunk * 2;
    C += (size_t)blockIdx.z * cStride;
    const int nst = kChunk >> 4;

    float acc[4][4][4];
    #pragma unroll
    for (int i = 0; i < 4; ++i)
        #pragma unroll
        for (int j = 0; j < 4; ++j)
            #pragma unroll
            for (int q = 0; q < 4; ++q) acc[i][j][q] = 0.0f;

    const int lr = wid * 16 + (lane & 7) + ((lane >> 4) << 3);
    const int ch = (lane >> 3) & 1;
    const uint32_t wo = (uint32_t)(lr * 32 + ((ch ^ ((lr >> 2) & 1)) << 4));
    const int gh = ch * 16;
    const char* pAh = (const char*)(Ahi + (size_t)(m0 + lr) * K) + kOffB + gh;
    const char* pAl = (const char*)(Alo + (size_t)(m0 + lr) * K) + kOffB + gh;
    const char* pBh = (const char*)(Bhi + (size_t)(n0 + lr) * K) + kOffB + gh;
    const char* pBl = (const char*)(Blo + (size_t)(n0 + lr) * K) + kOffB + gh;

    auto load_stage = [&](int s) {
        if (s < nst) {
            const uint32_t st = sb + (uint32_t)(s % NSTG) * STG;
            const int kb = s * 32;
            cpa16(st + wo, pAh + kb);
            cpa16(st + OA_LO + wo, pAl + kb);
            cpa16(st + OB_HI + wo, pBh + kb);
            cpa16(st + OB_LO + wo, pBl + kb);
        }
        asm volatile("cp.async.commit_group;");
    };

    load_stage(0);
    load_stage(1);
    load_stage(2);
    load_stage(3);

    const int rowA = wm * 64 + (lane & 15);
    const int cA = lane >> 4;
    const uint32_t aOff = (uint32_t)(rowA * 32 + ((cA ^ ((rowA >> 2) & 1)) << 4));
    const int rowB = wn * 32 + (lane & 7) + ((lane >> 4) << 3);
    const int cB = (lane >> 3) & 1;
    const uint32_t bOff = (uint32_t)(rowB * 32 + ((cB ^ ((rowB >> 2) & 1)) << 4));

    auto process_stage = [&](int s) {
        const uint32_t st = sb + (uint32_t)(s % NSTG) * STG;
        const uint32_t aB = st + aOff;
        const uint32_t bB = st + OB_HI + bOff;

        uint32_t ah[4][4], al[4][4], bh[2][4], bl[2][4];
        ldsm4(bh[0], bB);
        ldsm4(bh[1], bB + 512);
        #pragma unroll
        for (int i = 0; i < 4; ++i) ldsm4(ah[i], aB + i * 512);
        #pragma unroll
        for (int i = 0; i < 4; ++i) ldsm4(al[i], aB + OA_LO + i * 512);
        ldsm4(bl[0], bB + (OB_LO - OB_HI));
        ldsm4(bl[1], bB + (OB_LO - OB_HI) + 512);

        #pragma unroll
        for (int i = 0; i < 4; ++i)
            #pragma unroll
            for (int j = 0; j < 4; ++j)
                mma16816(acc[i][j], ah[i], &bh[j >> 1][(j & 1) * 2]);
        #pragma unroll
        for (int i = 0; i < 4; ++i)
            #pragma unroll
            for (int j = 0; j < 4; ++j)
                mma16816(acc[i][j], al[i], &bh[j >> 1][(j & 1) * 2]);
        #pragma unroll
        for (int i = 0; i < 4; ++i)
            #pragma unroll
            for (int j = 0; j < 4; ++j)
                mma16816(acc[i][j], ah[i], &bl[j >> 1][(j & 1) * 2]);
    };

    for (int p = 0; p < (nst >> 1); ++p) {
        asm volatile("cp.async.wait_group 2;");
        __syncthreads();
        load_stage(2*p + 4);
        load_stage(2*p + 5);
        process_stage(2*p);
        process_stage(2*p + 1);
    }

    #pragma unroll
    for (int i = 0; i < 4; ++i)
        #pragma unroll
        for (int j = 0; j < 4; ++j) {
            int row = m0 + wm*64 + i*16 + (lane >> 2);
            int col = n0 + wn*32 + j*8 + (lane & 3)*2;
            *(float2*)(C + (size_t)row * N + col) =
                make_float2(acc[i][j][0], acc[i][j][1]);
            *(float2*)(C + (size_t)(row + 8) * N + col) =
                make_float2(acc[i][j][2], acc[i][j][3]);
        }
}

// Reduce xproj split-K partials; also emits bf16 hi/lo of delta cols 0..63
__global__ void reduce_xdbl()
{
    int idx = blockIdx.x * blockDim.x + threadIdx.x;
    if (idx >= NR * 24) return;
    int m = idx / 24, c = (idx % 24) * 4;
    const float* p = g_xpart + (size_t)m * 128 + c;
    float4 s = make_float4(0.f, 0.f, 0.f, 0.f);
    #pragma unroll
    for (int z = 0; z < 8; ++z) {
        float4 v = *(const float4*)(p + (size_t)z * NR * 128);
        s.x += v.x; s.y += v.y; s.z += v.z; s.w += v.w;
    }
    *(float4*)(g_xdbl + (size_t)m * XD + c) = s;
    if (c < DR) {
        __nv_bfloat16 h0 = __float2bfloat16(s.x), h1 = __float2bfloat16(s.y);
        __nv_bfloat16 h2 = __float2bfloat16(s.z), h3 = __float2bfloat16(s.w);
        __nv_bfloat162* hp = (__nv_bfloat162*)(g_dthi + (size_t)m * DR + c);
        __nv_bfloat162* lp = (__nv_bfloat162*)(g_dtlo + (size_t)m * DR + c);
        hp[0] = __nv_bfloat162(h0, h1); hp[1] = __nv_bfloat162(h2, h3);
        lp[0] = __nv_bfloat162(__float2bfloat16(s.x - __bfloat162float(h0)),
                               __float2bfloat16(s.y - __bfloat162float(h1)));
        lp[1] = __nv_bfloat162(__float2bfloat16(s.z - __bfloat162float(h2)),
                               __float2bfloat16(s.w - __bfloat162float(h3)));
    }
}

// ---------------------------------------------------------------------------
// Causal depthwise conv (width 4) + bias + silu over xz[:, :, 0:DI].
// Writes bf16 hi/lo [B,L,DI] (for xproj HMMA) and fp32 transposed [B,DI,L].
// ---------------------------------------------------------------------------
__global__ void conv_silu_kernel(const float* __restrict__ conv_w,
                                 const float* __restrict__ conv_b)
{
    __shared__ float sIn[35][33];
    __shared__ float sOut[32][33];
    const int b = blockIdx.z, d0 = blockIdx.y * 32, l0 = blockIdx.x * 32;
    const int tid = threadIdx.x, tx = tid & 31, ty = tid >> 5;

    for (int r = ty; r < 35; r += 8) {
        int gl = l0 + r - 3;
        sIn[r][tx] = (gl >= 0) ? g_xz[(size_t)(b*LL + gl) * XZW + d0 + tx] : 0.0f;
    }
    __syncthreads();

    float4 w = *(const float4*)(conv_w + (d0 + tx) * 4);
    float cb = conv_b[d0 + tx];
    #pragma unroll
    for (int i = 0; i < 4; ++i) {
        int r = ty + i * 8;
        float v = sIn[r][tx]*w.x + sIn[r+1][tx]*w.y + sIn[r+2][tx]*w.z + sIn[r+3][tx]*w.w + cb;
        v = siluf(v);
        sOut[r][tx] = v;
        size_t idx = (size_t)(b*LL + l0 + r) * DI + d0 + tx;
        __nv_bfloat16 h = __float2bfloat16(v);
        g_xphi[idx] = h;
        g_xplo[idx] = __float2bfloat16(v - __bfloat162float(h));
    }
    __syncthreads();
    #pragma unroll
    for (int i = 0; i < 4; ++i) {
        int dd = ty + i * 8;
        g_xpt[(size_t)(b*DI + d0 + dd) * LL + l0 + tx] = sOut[tx][dd];
    }
}

// ---------------------------------------------------------------------------
// delta transpose + bias + softplus
// ---------------------------------------------------------------------------
__global__ void dtrans_kernel(const float* __restrict__ dtb)
{
    __shared__ float sD[32][33];
    const int b = blockIdx.z, n0 = blockIdx.y * 32, l0 = blockIdx.x * 32;
    const int tid = threadIdx.x, tx = tid & 31, ty = tid >> 5;

    #pragma unroll
    for (int i = 0; i < 4; ++i) {
        int r = ty + i * 8;
        sD[r][tx] = g_delta[(size_t)(b*LL + l0 + r) * DI + n0 + tx];
    }
    __syncthreads();
    #pragma unroll
    for (int i = 0; i < 4; ++i) {
        int ny = ty + i * 8;
        int n = n0 + ny;
        float v = softplusf(sD[tx][ny] + dtb[n]);
        g_dtt[(size_t)(b*DI + n) * LL + l0 + tx] = v;
    }
}

// ---------------------------------------------------------------------------
// Chunked selective scan, pass 1
// ---------------------------------------------------------------------------
__global__ __launch_bounds__(256)
void scan_pass1(const float* __restrict__ A_log)
{
    const int tid = threadIdx.x;
    const int ch = blockIdx.x * 32 + (tid >> 3);
    const int g  = tid & 7;
    const int c  = blockIdx.y;
    const int d  = ch & (DI - 1);
    const int b  = ch >> 11;
    const int n0 = g * 2;

    const float A0 = -__expf(A_log[d*DS + n0]);
    const float A1 = -__expf(A_log[d*DS + n0 + 1]);

    const float* __restrict__ dtp = g_dtt + (size_t)ch * LL + c * LC;
    const float* __restrict__ xpp = g_xpt + (size_t)ch * LL + c * LC;
    const float* __restrict__ rp  = g_xdbl + (size_t)(b*LL + c*LC) * XD + DR + n0;

    float h0 = 0.f, h1 = 0.f, sdt = 0.f;
    float dt[2][4], xv[2][4];
    float2 Bv[2][4];

    #pragma unroll
    for (int u = 0; u < 4; ++u) {
        dt[0][u] = __ldg(dtp + u);
        xv[0][u] = __ldg(xpp + u);
        Bv[0][u] = *(const float2*)(rp + (size_t)u * XD);
    }

    for (int l = 0; l < LC; l += 8) {
        #pragma unroll
        for (int u = 0; u < 4; ++u) {
            int ll = l + 4 + u;
            dt[1][u] = __ldg(dtp + ll);
            xv[1][u] = __ldg(xpp + ll);
            Bv[1][u] = *(const float2*)(rp + (size_t)ll * XD);
        }
        #pragma unroll
        for (int u = 0; u < 4; ++u) {
            float dtx = dt[0][u] * xv[0][u];
            h0 = fmaf(__expf(dt[0][u] * A0), h0, dtx * Bv[0][u].x);
            h1 = fmaf(__expf(dt[0][u] * A1), h1, dtx * Bv[0][u].y);
            sdt += dt[0][u];
        }
        int lp = (l + 8 < LC) ? l + 8 : 0;
        #pragma unroll
        for (int u = 0; u < 4; ++u) {
            int ll = lp + u;
            dt[0][u] = __ldg(dtp + ll);
            xv[0][u] = __ldg(xpp + ll);
            Bv[0][u] = *(const float2*)(rp + (size_t)ll * XD);
        }
        #pragma unroll
        for (int u = 0; u < 4; ++u) {
            float dtx = dt[1][u] * xv[1][u];
            h0 = fmaf(__expf(dt[1][u] * A0), h0, dtx * Bv[1][u].x);
            h1 = fmaf(__expf(dt[1][u] * A1), h1, dtx * Bv[1][u].y);
            sdt += dt[1][u];
        }
    }

    float* qp = g_q + ((size_t)c * (BB*DI) + ch) * DS + n0;
    qp[0] = h0; qp[1] = h1;
    if (g == 0) g_sdt[(size_t)c * (BB*DI) + ch] = sdt;
}

// ---------------------------------------------------------------------------
// Chunked selective scan, pass 2
// ---------------------------------------------------------------------------
__global__ __launch_bounds__(256)
void scan_pass2(const float* __restrict__ A_log, const float* __restrict__ Dv)
{
    const int tid = threadIdx.x;
    const int ch = blockIdx.x * 32 + (tid >> 3);
    const int g  = tid & 7;
    const int c  = blockIdx.y;
    const int d  = ch & (DI - 1);
    const int b  = ch >> 11;
    const int n0 = g * 2;

    const float A0 = -__expf(A_log[d*DS + n0]);
    const float A1 = -__expf(A_log[d*DS + n0 + 1]);
    const float Dd = Dv[d];

    float h0 = 0.f, h1 = 0.f;
    for (int j = 0; j < c; ++j) {
        float s = __ldg(g_sdt + (size_t)j * (BB*DI) + ch);
        const float* qp = g_q + ((size_t)j * (BB*DI) + ch) * DS + n0;
        h0 = fmaf(__expf(s * A0), h0, __ldg(qp));
        h1 = fmaf(__expf(s * A1), h1, __ldg(qp + 1));
    }

    const float* __restrict__ dtp = g_dtt + (size_t)ch * LL + c * LC;
    const float* __restrict__ xpp = g_xpt + (size_t)ch * LL + c * LC;
    const float* __restrict__ rp  = g_xdbl + (size_t)(b*LL + c*LC) * XD + DR + n0;
    float* __restrict__ yp = g_yt + (size_t)ch * LL + c * LC;

    float dt[2][4], xv[2][4];
    float2 Bv[2][4], Cv[2][4];

    #pragma unroll
    for (int u = 0; u < 4; ++u) {
        dt[0][u] = __ldg(dtp + u);
        xv[0][u] = __ldg(xpp + u);
        Bv[0][u] = *(const float2*)(rp + (size_t)u * XD);
        Cv[0][u] = *(const float2*)(rp + (size_t)u * XD + DS);
    }

    for (int l = 0; l < LC; l += 8) {
        #pragma unroll
        for (int u = 0; u < 4; ++u) {
            int ll = l + 4 + u;
            dt[1][u] = __ldg(dtp + ll);
            xv[1][u] = __ldg(xpp + ll);
            Bv[1][u] = *(const float2*)(rp + (size_t)ll * XD);
            Cv[1][u] = *(const float2*)(rp + (size_t)ll * XD + DS);
        }
        #pragma unroll
        for (int u = 0; u < 4; ++u) {
            float dtx = dt[0][u] * xv[0][u];
            h0 = fmaf(__expf(dt[0][u] * A0), h0, dtx * Bv[0][u].x);
            h1 = fmaf(__expf(dt[0][u] * A1), h1, dtx * Bv[0][u].y);
            float y = fmaf(h0, Cv[0][u].x, h1 * Cv[0][u].y);
            y += __shfl_down_sync(0xffffffffu, y, 4, 8);
            y += __shfl_down_sync(0xffffffffu, y, 2, 8);
            y += __shfl_down_sync(0xffffffffu, y, 1, 8);
            if (g == 0) yp[l + u] = fmaf(Dd, xv[0][u], y);
        }
        int lp = (l + 8 < LC) ? l + 8 : 0;
        #pragma unroll
        for (int u = 0; u < 4; ++u) {
            int ll = lp + u;
            dt[0][u] = __ldg(dtp + ll);
            xv[0][u] = __ldg(xpp + ll);
            Bv[0][u] = *(const float2*)(rp + (size_t)ll * XD);
            Cv[0][u] = *(const float2*)(rp + (size_t)ll * XD + DS);
        }
        #pragma unroll
        for (int u = 0; u < 4; ++u) {
            float dtx = dt[1][u] * xv[1][u];
            h0 = fmaf(__expf(dt[1][u] * A0), h0, dtx * Bv[1][u].x);
            h1 = fmaf(__expf(dt[1][u] * A1), h1, dtx * Bv[1][u].y);
            float y = fmaf(h0, Cv[1][u].x, h1 * Cv[1][u].y);
            y += __shfl_down_sync(0xffffffffu, y, 4, 8);
            y += __shfl_down_sync(0xffffffffu, y, 2, 8);
            y += __shfl_down_sync(0xffffffffu, y, 1, 8);
            if (g == 0) yp[l + 4 + u] = fmaf(Dd, xv[1][u], y);
        }
    }
}

// ---------------------------------------------------------------------------
// g = y_t * silu(z) -> fp16 single (A operand of out_proj 2-pass GEMM)
// ---------------------------------------------------------------------------
__global__ void gmul_cast_kernel()
{
    __shared__ float sY[32][33];
    const int b = blockIdx.z, d0 = blockIdx.y * 32, l0 = blockIdx.x * 32;
    const int tid = threadIdx.x, tx = tid & 31, ty = tid >> 5;

    #pragma unroll
    for (int i = 0; i < 4; ++i) {
        int dd = ty + i * 8;
        sY[dd][tx] = g_yt[(size_t)(b*DI + d0 + dd) * LL + l0 + tx];
    }
    __syncthreads();
    #pragma unroll
    for (int i = 0; i < 4; ++i) {
        int r = ty + i * 8;
        float z = g_xz[(size_t)(b*LL + l0 + r) * XZW + DI + d0 + tx];
        float v = sY[tx][r] * siluf(z);
        g_gh[(size_t)(b*LL + l0 + r) * DI + d0 + tx] = __float2half_rn(v);
    }
}

// ---------------------------------------------------------------------------
extern "C" void kernel_launch(void* const* d_in, const int* in_sizes, int n_in,
                              void* d_out, int out_size)
{
    const float* x       = (const float*)d_in[0];
    const float* in_proj = (const float*)d_in[1];
    const float* conv_w  = (const float*)d_in[2];
    const float* conv_b  = (const float*)d_in[3];
    const float* x_proj  = (const float*)d_in[4];
    const float* dt_w    = (const float*)d_in[5];
    const float* dt_b    = (const float*)d_in[6];
    const float* A_log   = (const float*)d_in[7];
    const float* Dv      = (const float*)d_in[8];
    const float* out_w   = (const float*)d_in[9];
    float* out = (float*)d_out;

    float *xz, *xpart, *delta;
    __nv_bfloat16 *xphi, *xplo, *w3hi, *w3lo, *dthi, *dtlo, *wdhi, *wdlo;
    __half *xh, *w1h, *w1l, *ghp, *w2h, *w2l;
    cudaGetSymbolAddress((void**)&xz,    g_xz);
    cudaGetSymbolAddress((void**)&xpart, g_xpart);
    cudaGetSymbolAddress((void**)&delta, g_delta);
    cudaGetSymbolAddress((void**)&xphi,  g_xphi);
    cudaGetSymbolAddress((void**)&xplo,  g_xplo);
    cudaGetSymbolAddress((void**)&w3hi,  g_w3hi);
    cudaGetSymbolAddress((void**)&w3lo,  g_w3lo);
    cudaGetSymbolAddress((void**)&dthi,  g_dthi);
    cudaGetSymbolAddress((void**)&dtlo,  g_dtlo);
    cudaGetSymbolAddress((void**)&wdhi,  g_wdhi);
    cudaGetSymbolAddress((void**)&wdlo,  g_wdlo);
    cudaGetSymbolAddress((void**)&xh,    g_xh);
    cudaGetSymbolAddress((void**)&w1h,   g_w1h);
    cudaGetSymbolAddress((void**)&w1l,   g_w1l);
    cudaGetSymbolAddress((void**)&ghp,   g_gh);
    cudaGetSymbolAddress((void**)&w2h,   g_w2h);
    cudaGetSymbolAddress((void**)&w2l,   g_w2l);

    cudaFuncSetAttribute(hmma_gemm,  cudaFuncAttributeMaxDynamicSharedMemorySize, HM_SMEM);
    cudaFuncSetAttribute(hmma2_gemm, cudaFuncAttributeMaxDynamicSharedMemorySize, H2_SMEM);

    // 0-2) conversions (so in_proj hmma2 sits at launch index 3 for ncu)
    cast_f16<<<(NR*DM/4 + 255)/256, 256>>>(x, xh, NR*DM/4);
    split_f16<<<(XZW*DM/4 + 255)/256, 256>>>(in_proj, w1h, w1l, XZW*DM/4);
    split_f16<<<(DM*DI/4 + 255)/256, 256>>>(out_w, w2h, w2l, DM*DI/4);
    // 3) xz = x @ in_proj_w^T  (2-pass fp16) -> [4096, 4096]
    hmma2_gemm<<<dim3(XZW/128, NR/128), 256, H2_SMEM>>>(xh, w1h, w1l, xz, XZW, DM);
    // 4) conv + silu (writes bf16 hi/lo + fp32 transposed)
    conv_silu_kernel<<<dim3(LL/32, DI/32, BB), 256>>>(conv_w, conv_b);
    // 5) pad+split x_proj_w; split dt_proj_w (bf16 3-pass path)
    split_pad_xw<<<(128*DI/4 + 255)/256, 256>>>(x_proj);
    split_bf16<<<(DI*DR/4 + 255)/256, 256>>>(dt_w, wdhi, wdlo, DI*DR/4);
    // 6) x_dbl partials = x_p @ x_proj_w^T (bf16 3-pass, split-K x8)
    hmma_gemm<<<dim3(1, NR/128, 8), 256, HM_SMEM>>>(
        xphi, xplo, w3hi, w3lo, xpart, 128, DI, DI/8, (size_t)NR*128);
    // 7) reduce partials -> g_xdbl; bf16-split delta cols
    reduce_xdbl<<<(NR*24 + 255)/256, 256>>>();
    // 8) delta raw = x_dbl[:, :64] @ dt_proj_w^T (bf16 3-pass)
    hmma_gemm<<<dim3(DI/128, NR/128, 1), 256, HM_SMEM>>>(
        dthi, dtlo, wdhi, wdlo, delta, DI, DR, DR, 0);
    // 9) softplus(delta + bias), transposed
    dtrans_kernel<<<dim3(LL/32, DI/32, BB), 256>>>(dt_b);
    // 10) chunked selective scan (16 chunks of 128)
    scan_pass1<<<dim3((BB*DI)/32, NCH-1), 256>>>(A_log);
    scan_pass2<<<dim3((BB*DI)/32, NCH), 256>>>(A_log, Dv);
    // 11) g = y * silu(z) -> fp16
    gmul_cast_kernel<<<dim3(LL/32, DI/32, BB), 256>>>();
    // 12) out = g @ out_proj_w^T (2-pass fp16)
    hmma2_gemm<<<dim3(DM/128, NR/128), 256, H2_SMEM>>>(ghp, w2h, w2l, out, DM, DI);
}

// round 17
// speedup vs baseline: 2.3523x; 1.0061x over previous
#include <cuda_runtime.h>
#include <cuda_fp16.h>
#include <cstdint>
#include <math.h>

// Problem constants (fixed by reference)
#define BB 2
#define LL 2048
#define DM 1024
#define DI 2048
#define DS 16
#define DR 64
#define NR (BB*LL)     // 4096 rows (b,l)
#define XZW (2*DI)     // 4096
#define XD  96         // dt_rank + 2*d_state
#define NCH 16
#define LC (LL/NCH)    // 128

// Scratch (device globals; no allocation allowed)
__device__ float g_xz  [(size_t)NR*XZW];   // in_proj output [B,L,2*DI]
__device__ float g_xpt [(size_t)BB*DI*LL]; // conv+silu output transposed [B,DI,L]
__device__ float g_xdbl[(size_t)NR*XD];    // x_proj output [B,L,96]
__device__ float g_dtt [(size_t)BB*DI*LL]; // softplus(delta) transposed [B,DI,L]
__device__ float g_yt  [(size_t)BB*DI*LL]; // scan output (+D*x) [B,DI,L]
__device__ float g_xpart[(size_t)8*NR*128];// xproj split-K partials [8][4096][128]
__device__ float g_delta[(size_t)NR*DI];   // raw delta GEMM output [B,L,DI]
__device__ float g_q   [(size_t)(NCH-1)*BB*DI*DS]; // pass1 final states
__device__ float g_sdt [(size_t)(NCH-1)*BB*DI];    // pass1 per-chunk sum(dt)

// fp16 buffers
//   in/out_proj: 2-pass (A single, B split)  — error ~1.2e-4, linear paths
//   xproj/delta: 3-pass (A split, B split)   — error ~2e-7, scan-input path
__device__ __half g_xh  [(size_t)NR*DM];   // x fp16 (in_proj A)
__device__ __half g_w1h [(size_t)XZW*DM];  // in_proj_w hi
__device__ __half g_w1l [(size_t)XZW*DM];  // in_proj_w lo
__device__ __half g_xph [(size_t)NR*DI];   // conv+silu out hi (xproj A)
__device__ __half g_xpl [(size_t)NR*DI];   // conv+silu out lo
__device__ __half g_w3h [(size_t)128*DI];  // x_proj_w padded, hi
__device__ __half g_w3l [(size_t)128*DI];  // lo
__device__ __half g_dth [(size_t)NR*DR];   // x_dbl[:, :64] hi (delta A)
__device__ __half g_dtl [(size_t)NR*DR];   // lo
__device__ __half g_wdh [(size_t)DI*DR];   // dt_proj_w hi
__device__ __half g_wdl [(size_t)DI*DR];   // dt_proj_w lo
__device__ __half g_gh  [(size_t)NR*DI];   // g fp16 (out_proj A)
__device__ __half g_w2h [(size_t)DM*DI];   // out_proj_w hi
__device__ __half g_w2l [(size_t)DM*DI];   // out_proj_w lo

__device__ __forceinline__ float siluf(float x) { return x / (1.0f + __expf(-x)); }
__device__ __forceinline__ float softplusf(float x) {
    return (x > 20.0f) ? x : log1pf(__expf(x));
}

// ===========================================================================
// Base-target (sm_103, no 'a') tensor path: ldmatrix + mma.sync + cp.async
// ===========================================================================
__device__ __forceinline__ uint32_t smem_u32(const void* p) {
    uint32_t a;
    asm("{ .reg .u64 t; cvta.to.shared.u64 t, %1; cvt.u32.u64 %0, t; }" : "=r"(a) : "l"(p));
    return a;
}
__device__ __forceinline__ void cpa16(uint32_t dst, const void* src) {
    asm volatile("cp.async.cg.shared.global [%0], [%1], 16;" :: "r"(dst), "l"(src));
}
__device__ __forceinline__ void ldsm4(uint32_t* r, uint32_t a) {
    asm volatile("ldmatrix.sync.aligned.m8n8.x4.shared.b16 {%0,%1,%2,%3}, [%4];"
                 : "=r"(r[0]), "=r"(r[1]), "=r"(r[2]), "=r"(r[3]) : "r"(a));
}
__device__ __forceinline__ void mmaf16(float* c, const uint32_t* a, const uint32_t* b) {
    asm volatile("mma.sync.aligned.m16n8k16.row.col.f32.f16.f16.f32 "
                 "{%0,%1,%2,%3}, {%4,%5,%6,%7}, {%8,%9}, {%0,%1,%2,%3};"
                 : "+f"(c[0]), "+f"(c[1]), "+f"(c[2]), "+f"(c[3])
                 : "r"(a[0]), "r"(a[1]), "r"(a[2]), "r"(a[3]), "r"(b[0]), "r"(b[1]));
}

// ===========================================================================
// fp32 -> fp16 single cast (A operands of 2-pass GEMMs)
// ===========================================================================
__global__ void cast_f16(const float* __restrict__ in, __half* __restrict__ out, int n4)
{
    int i = blockIdx.x * blockDim.x + threadIdx.x;
    if (i >= n4) return;
    float4 v = *(const float4*)(in + (size_t)i * 4);
    __half2* op = (__half2*)(out + (size_t)i * 4);
    op[0] = __floats2half2_rn(v.x, v.y);
    op[1] = __floats2half2_rn(v.z, v.w);
}

// fp32 -> fp16 hi + fp16 lo (residual)
__global__ void split_f16(const float* __restrict__ in, __half* __restrict__ hi,
                          __half* __restrict__ lo, int n4)
{
    int i = blockIdx.x * blockDim.x + threadIdx.x;
    if (i >= n4) return;
    float4 v = *(const float4*)(in + (size_t)i * 4);
    __half h0 = __float2half_rn(v.x), h1 = __float2half_rn(v.y);
    __half h2 = __float2half_rn(v.z), h3 = __float2half_rn(v.w);
    __half2* hp = (__half2*)(hi + (size_t)i * 4);
    __half2* lp = (__half2*)(lo + (size_t)i * 4);
    hp[0] = __half2(h0, h1); hp[1] = __half2(h2, h3);
    lp[0] = __floats2half2_rn(v.x - __half2float(h0), v.y - __half2float(h1));
    lp[1] = __floats2half2_rn(v.z - __half2float(h2), v.w - __half2float(h3));
}

// Split + zero-pad x_proj_w [96,2048] -> [128,2048] fp16 hi/lo
__global__ void split_pad_xw(const float* __restrict__ xw)
{
    int i = blockIdx.x * blockDim.x + threadIdx.x;
    if (i >= 128 * DI / 4) return;
    int row = i >> 9;
    float4 v = make_float4(0.f, 0.f, 0.f, 0.f);
    if (row < 96) v = *(const float4*)(xw + (size_t)i * 4);
    __half h0 = __float2half_rn(v.x), h1 = __float2half_rn(v.y);
    __half h2 = __float2half_rn(v.z), h3 = __float2half_rn(v.w);
    __half2* hp = (__half2*)(g_w3h + (size_t)i * 4);
    __half2* lp = (__half2*)(g_w3l + (size_t)i * 4);
    hp[0] = __half2(h0, h1); hp[1] = __half2(h2, h3);
    lp[0] = __floats2half2_rn(v.x - __half2float(h0), v.y - __half2float(h1));
    lp[1] = __floats2half2_rn(v.z - __half2float(h2), v.w - __half2float(h3));
}

// ===========================================================================
// 2-pass fp16 HMMA GEMM v6: C = A @ (Bhi + Blo)^T (in_proj / out_proj).
// CTA 128x128, warp tile 64x32 (8 warps). Stage K=16 = 12KB; 8-deep ring,
// barrier per two stages (wait_group 4), packed-32B rows + XOR swizzle.
// ===========================================================================
#define F_BH 4096
#define F_BL 8192
#define F_STG 12288
#define F_NSTG 8
#define H2_SMEM (F_NSTG*F_STG)  // 98304

__global__ void __launch_bounds__(256, 2)
hmma2_gemm(const __half* __restrict__ A, const __half* __restrict__ Bhi,
           const __half* __restrict__ Blo, float* __restrict__ C, int N, int K)
{
    extern __shared__ char sm2_[];
    const uint32_t sb = smem_u32(sm2_);
    const int tid = threadIdx.x, lane = tid & 31, wid = tid >> 5;
    const int wm = wid >> 2, wn = wid & 3;
    const int m0 = blockIdx.y * 128, n0 = blockIdx.x * 128;
    const int nst = K >> 4;

    float acc[4][4][4];
    #pragma unroll
    for (int i = 0; i < 4; ++i)
        #pragma unroll
        for (int j = 0; j < 4; ++j)
            #pragma unroll
            for (int q = 0; q < 4; ++q) acc[i][j][q] = 0.0f;

    const int lr = wid * 16 + (lane & 7) + ((lane >> 4) << 3);
    const int ch = (lane >> 3) & 1;
    const uint32_t wo = (uint32_t)(lr * 32 + ((ch ^ ((lr >> 2) & 1)) << 4));
    const int gh = ch * 16;
    const char* pA  = (const char*)(A   + (size_t)(m0 + lr) * K) + gh;
    const char* pBh = (const char*)(Bhi + (size_t)(n0 + lr) * K) + gh;
    const char* pBl = (const char*)(Blo + (size_t)(n0 + lr) * K) + gh;

    auto load_stage = [&](int s) {
        if (s < nst) {
            const uint32_t st = sb + (uint32_t)(s % F_NSTG) * F_STG;
            const int kb = s * 32;
            cpa16(st + wo, pA + kb);
            cpa16(st + F_BH + wo, pBh + kb);
            cpa16(st + F_BL + wo, pBl + kb);
        }
        asm volatile("cp.async.commit_group;");
    };

    load_stage(0); load_stage(1); load_stage(2);
    load_stage(3); load_stage(4); load_stage(5);

    const int rowA = wm * 64 + (lane & 15);
    const int cA = lane >> 4;
    const uint32_t aOff = (uint32_t)(rowA * 32 + ((cA ^ ((rowA >> 2) & 1)) << 4));
    const int rowB = wn * 32 + (lane & 7) + ((lane >> 4) << 3);
    const int cB = (lane >> 3) & 1;
    const uint32_t bOff = (uint32_t)(rowB * 32 + ((cB ^ ((rowB >> 2) & 1)) << 4));

    auto process_stage = [&](int s) {
        const uint32_t st = sb + (uint32_t)(s % F_NSTG) * F_STG;
        const uint32_t aB = st + aOff;
        const uint32_t bB = st + F_BH + bOff;

        uint32_t ah[4][4], bh[2][4], bl[2][4];
        ldsm4(bh[0], bB);
        ldsm4(bh[1], bB + 512);
        #pragma unroll
        for (int i = 0; i < 4; ++i) ldsm4(ah[i], aB + i * 512);
        ldsm4(bl[0], bB + (F_BL - F_BH));
        ldsm4(bl[1], bB + (F_BL - F_BH) + 512);

        #pragma unroll
        for (int i = 0; i < 4; ++i)
            #pragma unroll
            for (int j = 0; j < 4; ++j)
                mmaf16(acc[i][j], ah[i], &bh[j >> 1][(j & 1) * 2]);
        #pragma unroll
        for (int i = 0; i < 4; ++i)
            #pragma unroll
            for (int j = 0; j < 4; ++j)
                mmaf16(acc[i][j], ah[i], &bl[j >> 1][(j & 1) * 2]);
    };

    for (int p = 0; p < (nst >> 1); ++p) {
        asm volatile("cp.async.wait_group 4;");
        __syncthreads();
        load_stage(2*p + 6);
        load_stage(2*p + 7);
        process_stage(2*p);
        process_stage(2*p + 1);
    }

    #pragma unroll
    for (int i = 0; i < 4; ++i)
        #pragma unroll
        for (int j = 0; j < 4; ++j) {
            int row = m0 + wm*64 + i*16 + (lane >> 2);
            int col = n0 + wn*32 + j*8 + (lane & 3)*2;
            *(float2*)(C + (size_t)row * N + col) =
                make_float2(acc[i][j][0], acc[i][j][1]);
            *(float2*)(C + (size_t)(row + 8) * N + col) =
                make_float2(acc[i][j][2], acc[i][j][3]);
        }
}

// ===========================================================================
// 3-pass fp16 HMMA GEMM v7: C = (Ahi+Alo) @ (Bhi+Blo)^T (xproj / delta).
// Drops only Alo*Blo (~2^-24). Same tiling as v6 but 4 smem planes,
// stage 16KB, 6-deep ring, barrier per two stages (wait_group 2).
// Split-K via blockIdx.z.
// ===========================================================================
#define T_AL 4096
#define T_BH 8192
#define T_BL 12288
#define T_STG 16384
#define T_NSTG 6
#define H3_SMEM (T_NSTG*T_STG)  // 98304

__global__ void __launch_bounds__(256, 2)
hmma3_gemm(const __half* __restrict__ Ahi, const __half* __restrict__ Alo,
           const __half* __restrict__ Bhi, const __half* __restrict__ Blo,
           float* __restrict__ C, int N, int K, int kChunk, size_t cStride)
{
    extern __shared__ char sm3_[];
    const uint32_t sb = smem_u32(sm3_);
    const int tid = threadIdx.x, lane = tid & 31, wid = tid >> 5;
    const int wm = wid >> 2, wn = wid & 3;
    const int m0 = blockIdx.y * 128, n0 = blockIdx.x * 128;
    const int kOffB = blockIdx.z * kChunk * 2;
    C += (size_t)blockIdx.z * cStride;
    const int nst = kChunk >> 4;

    float acc[4][4][4];
    #pragma unroll
    for (int i = 0; i < 4; ++i)
        #pragma unroll
        for (int j = 0; j < 4; ++j)
            #pragma unroll
            for (int q = 0; q < 4; ++q) acc[i][j][q] = 0.0f;

    const int lr = wid * 16 + (lane & 7) + ((lane >> 4) << 3);
    const int ch = (lane >> 3) & 1;
    const uint32_t wo = (uint32_t)(lr * 32 + ((ch ^ ((lr >> 2) & 1)) << 4));
    const int gh = ch * 16;
    const char* pAh = (const char*)(Ahi + (size_t)(m0 + lr) * K) + kOffB + gh;
    const char* pAl = (const char*)(Alo + (size_t)(m0 + lr) * K) + kOffB + gh;
    const char* pBh = (const char*)(Bhi + (size_t)(n0 + lr) * K) + kOffB + gh;
    const char* pBl = (const char*)(Blo + (size_t)(n0 + lr) * K) + kOffB + gh;

    auto load_stage = [&](int s) {
        if (s < nst) {
            const uint32_t st = sb + (uint32_t)(s % T_NSTG) * T_STG;
            const int kb = s * 32;
            cpa16(st + wo, pAh + kb);
            cpa16(st + T_AL + wo, pAl + kb);
            cpa16(st + T_BH + wo, pBh + kb);
            cpa16(st + T_BL + wo, pBl + kb);
        }
        asm volatile("cp.async.commit_group;");
    };

    load_stage(0);
    load_stage(1);
    load_stage(2);
    load_stage(3);

    const int rowA = wm * 64 + (lane & 15);
    const int cA = lane >> 4;
    const uint32_t aOff = (uint32_t)(rowA * 32 + ((cA ^ ((rowA >> 2) & 1)) << 4));
    const int rowB = wn * 32 + (lane & 7) + ((lane >> 4) << 3);
    const int cB = (lane >> 3) & 1;
    const uint32_t bOff = (uint32_t)(rowB * 32 + ((cB ^ ((rowB >> 2) & 1)) << 4));

    auto process_stage = [&](int s) {
        const uint32_t st = sb + (uint32_t)(s % T_NSTG) * T_STG;
        const uint32_t aB = st + aOff;
        const uint32_t bB = st + T_BH + bOff;

        uint32_t ah[4][4], al[4][4], bh[2][4], bl[2][4];
        ldsm4(bh[0], bB);
        ldsm4(bh[1], bB + 512);
        #pragma unroll
        for (int i = 0; i < 4; ++i) ldsm4(ah[i], aB + i * 512);
        #pragma unroll
        for (int i = 0; i < 4; ++i) ldsm4(al[i], aB + T_AL + i * 512);
        ldsm4(bl[0], bB + (T_BL - T_BH));
        ldsm4(bl[1], bB + (T_BL - T_BH) + 512);

        #pragma unroll
        for (int i = 0; i < 4; ++i)
            #pragma unroll
            for (int j = 0; j < 4; ++j)
                mmaf16(acc[i][j], ah[i], &bh[j >> 1][(j & 1) * 2]);
        #pragma unroll
        for (int i = 0; i < 4; ++i)
            #pragma unroll
            for (int j = 0; j < 4; ++j)
                mmaf16(acc[i][j], al[i], &bh[j >> 1][(j & 1) * 2]);
        #pragma unroll
        for (int i = 0; i < 4; ++i)
            #pragma unroll
            for (int j = 0; j < 4; ++j)
                mmaf16(acc[i][j], ah[i], &bl[j >> 1][(j & 1) * 2]);
    };

    for (int p = 0; p < (nst >> 1); ++p) {
        asm volatile("cp.async.wait_group 2;");
        __syncthreads();
        load_stage(2*p + 4);
        load_stage(2*p + 5);
        process_stage(2*p);
        process_stage(2*p + 1);
    }

    #pragma unroll
    for (int i = 0; i < 4; ++i)
        #pragma unroll
        for (int j = 0; j < 4; ++j) {
            int row = m0 + wm*64 + i*16 + (lane >> 2);
            int col = n0 + wn*32 + j*8 + (lane & 3)*2;
            *(float2*)(C + (size_t)row * N + col) =
                make_float2(acc[i][j][0], acc[i][j][1]);
            *(float2*)(C + (size_t)(row + 8) * N + col) =
                make_float2(acc[i][j][2], acc[i][j][3]);
        }
}

// Reduce xproj split-K partials: g_xdbl[m][c] = sum_z g_xpart[z][m][c], c<96.
// Also emits fp16 hi/lo of cols 0..63 (delta GEMM A operand).
__global__ void reduce_xdbl()
{
    int idx = blockIdx.x * blockDim.x + threadIdx.x;
    if (idx >= NR * 24) return;
    int m = idx / 24, c = (idx % 24) * 4;
    const float* p = g_xpart + (size_t)m * 128 + c;
    float4 s = make_float4(0.f, 0.f, 0.f, 0.f);
    #pragma unroll
    for (int z = 0; z < 8; ++z) {
        float4 v = *(const float4*)(p + (size_t)z * NR * 128);
        s.x += v.x; s.y += v.y; s.z += v.z; s.w += v.w;
    }
    *(float4*)(g_xdbl + (size_t)m * XD + c) = s;
    if (c < DR) {
        __half h0 = __float2half_rn(s.x), h1 = __float2half_rn(s.y);
        __half h2 = __float2half_rn(s.z), h3 = __float2half_rn(s.w);
        __half2* hp = (__half2*)(g_dth + (size_t)m * DR + c);
        __half2* lp = (__half2*)(g_dtl + (size_t)m * DR + c);
        hp[0] = __half2(h0, h1); hp[1] = __half2(h2, h3);
        lp[0] = __floats2half2_rn(s.x - __half2float(h0), s.y - __half2float(h1));
        lp[1] = __floats2half2_rn(s.z - __half2float(h2), s.w - __half2float(h3));
    }
}

// ---------------------------------------------------------------------------
// Causal depthwise conv (width 4) + bias + silu over xz[:, :, 0:DI].
// Writes fp16 hi/lo [B,L,DI] (xproj A) and fp32 transposed [B,DI,L].
// ---------------------------------------------------------------------------
__global__ void conv_silu_kernel(const float* __restrict__ conv_w,
                                 const float* __restrict__ conv_b)
{
    __shared__ float sIn[35][33];
    __shared__ float sOut[32][33];
    const int b = blockIdx.z, d0 = blockIdx.y * 32, l0 = blockIdx.x * 32;
    const int tid = threadIdx.x, tx = tid & 31, ty = tid >> 5;

    for (int r = ty; r < 35; r += 8) {
        int gl = l0 + r - 3;
        sIn[r][tx] = (gl >= 0) ? g_xz[(size_t)(b*LL + gl) * XZW + d0 + tx] : 0.0f;
    }
    __syncthreads();

    float4 w = *(const float4*)(conv_w + (d0 + tx) * 4);
    float cb = conv_b[d0 + tx];
    #pragma unroll
    for (int i = 0; i < 4; ++i) {
        int r = ty + i * 8;
        float v = sIn[r][tx]*w.x + sIn[r+1][tx]*w.y + sIn[r+2][tx]*w.z + sIn[r+3][tx]*w.w + cb;
        v = siluf(v);
        sOut[r][tx] = v;
        size_t idx = (size_t)(b*LL + l0 + r) * DI + d0 + tx;
        __half h = __float2half_rn(v);
        g_xph[idx] = h;
        g_xpl[idx] = __float2half_rn(v - __half2float(h));
    }
    __syncthreads();
    #pragma unroll
    for (int i = 0; i < 4; ++i) {
        int dd = ty + i * 8;
        g_xpt[(size_t)(b*DI + d0 + dd) * LL + l0 + tx] = sOut[tx][dd];
    }
}

// ---------------------------------------------------------------------------
// delta transpose + bias + softplus
// ---------------------------------------------------------------------------
__global__ void dtrans_kernel(const float* __restrict__ dtb)
{
    __shared__ float sD[32][33];
    const int b = blockIdx.z, n0 = blockIdx.y * 32, l0 = blockIdx.x * 32;
    const int tid = threadIdx.x, tx = tid & 31, ty = tid >> 5;

    #pragma unroll
    for (int i = 0; i < 4; ++i) {
        int r = ty + i * 8;
        sD[r][tx] = g_delta[(size_t)(b*LL + l0 + r) * DI + n0 + tx];
    }
    __syncthreads();
    #pragma unroll
    for (int i = 0; i < 4; ++i) {
        int ny = ty + i * 8;
        int n = n0 + ny;
        float v = softplusf(sD[tx][ny] + dtb[n]);
        g_dtt[(size_t)(b*DI + n) * LL + l0 + tx] = v;
    }
}

// ---------------------------------------------------------------------------
// Chunked selective scan, pass 1
// ---------------------------------------------------------------------------
__global__ __launch_bounds__(256)
void scan_pass1(const float* __restrict__ A_log)
{
    const int tid = threadIdx.x;
    const int ch = blockIdx.x * 32 + (tid >> 3);
    const int g  = tid & 7;
    const int c  = blockIdx.y;
    const int d  = ch & (DI - 1);
    const int b  = ch >> 11;
    const int n0 = g * 2;

    const float A0 = -__expf(A_log[d*DS + n0]);
    const float A1 = -__expf(A_log[d*DS + n0 + 1]);

    const float* __restrict__ dtp = g_dtt + (size_t)ch * LL + c * LC;
    const float* __restrict__ xpp = g_xpt + (size_t)ch * LL + c * LC;
    const float* __restrict__ rp  = g_xdbl + (size_t)(b*LL + c*LC) * XD + DR + n0;

    float h0 = 0.f, h1 = 0.f, sdt = 0.f;
    float dt[2][4], xv[2][4];
    float2 Bv[2][4];

    #pragma unroll
    for (int u = 0; u < 4; ++u) {
        dt[0][u] = __ldg(dtp + u);
        xv[0][u] = __ldg(xpp + u);
        Bv[0][u] = *(const float2*)(rp + (size_t)u * XD);
    }

    for (int l = 0; l < LC; l += 8) {
        #pragma unroll
        for (int u = 0; u < 4; ++u) {
            int ll = l + 4 + u;
            dt[1][u] = __ldg(dtp + ll);
            xv[1][u] = __ldg(xpp + ll);
            Bv[1][u] = *(const float2*)(rp + (size_t)ll * XD);
        }
        #pragma unroll
        for (int u = 0; u < 4; ++u) {
            float dtx = dt[0][u] * xv[0][u];
            h0 = fmaf(__expf(dt[0][u] * A0), h0, dtx * Bv[0][u].x);
            h1 = fmaf(__expf(dt[0][u] * A1), h1, dtx * Bv[0][u].y);
            sdt += dt[0][u];
        }
        int lp = (l + 8 < LC) ? l + 8 : 0;
        #pragma unroll
        for (int u = 0; u < 4; ++u) {
            int ll = lp + u;
            dt[0][u] = __ldg(dtp + ll);
            xv[0][u] = __ldg(xpp + ll);
            Bv[0][u] = *(const float2*)(rp + (size_t)ll * XD);
        }
        #pragma unroll
        for (int u = 0; u < 4; ++u) {
            float dtx = dt[1][u] * xv[1][u];
            h0 = fmaf(__expf(dt[1][u] * A0), h0, dtx * Bv[1][u].x);
            h1 = fmaf(__expf(dt[1][u] * A1), h1, dtx * Bv[1][u].y);
            sdt += dt[1][u];
        }
    }

    float* qp = g_q + ((size_t)c * (BB*DI) + ch) * DS + n0;
    qp[0] = h0; qp[1] = h1;
    if (g == 0) g_sdt[(size_t)c * (BB*DI) + ch] = sdt;
}

// ---------------------------------------------------------------------------
// Chunked selective scan, pass 2
// ---------------------------------------------------------------------------
__global__ __launch_bounds__(256)
void scan_pass2(const float* __restrict__ A_log, const float* __restrict__ Dv)
{
    const int tid = threadIdx.x;
    const int ch = blockIdx.x * 32 + (tid >> 3);
    const int g  = tid & 7;
    const int c  = blockIdx.y;
    const int d  = ch & (DI - 1);
    const int b  = ch >> 11;
    const int n0 = g * 2;

    const float A0 = -__expf(A_log[d*DS + n0]);
    const float A1 = -__expf(A_log[d*DS + n0 + 1]);
    const float Dd = Dv[d];

    float h0 = 0.f, h1 = 0.f;
    for (int j = 0; j < c; ++j) {
        float s = __ldg(g_sdt + (size_t)j * (BB*DI) + ch);
        const float* qp = g_q + ((size_t)j * (BB*DI) + ch) * DS + n0;
        h0 = fmaf(__expf(s * A0), h0, __ldg(qp));
        h1 = fmaf(__expf(s * A1), h1, __ldg(qp + 1));
    }

    const float* __restrict__ dtp = g_dtt + (size_t)ch * LL + c * LC;
    const float* __restrict__ xpp = g_xpt + (size_t)ch * LL + c * LC;
    const float* __restrict__ rp  = g_xdbl + (size_t)(b*LL + c*LC) * XD + DR + n0;
    float* __restrict__ yp = g_yt + (size_t)ch * LL + c * LC;

    float dt[2][4], xv[2][4];
    float2 Bv[2][4], Cv[2][4];

    #pragma unroll
    for (int u = 0; u < 4; ++u) {
        dt[0][u] = __ldg(dtp + u);
        xv[0][u] = __ldg(xpp + u);
        Bv[0][u] = *(const float2*)(rp + (size_t)u * XD);
        Cv[0][u] = *(const float2*)(rp + (size_t)u * XD + DS);
    }

    for (int l = 0; l < LC; l += 8) {
        #pragma unroll
        for (int u = 0; u < 4; ++u) {
            int ll = l + 4 + u;
            dt[1][u] = __ldg(dtp + ll);
            xv[1][u] = __ldg(xpp + ll);
            Bv[1][u] = *(const float2*)(rp + (size_t)ll * XD);
            Cv[1][u] = *(const float2*)(rp + (size_t)ll * XD + DS);
        }
        #pragma unroll
        for (int u = 0; u < 4; ++u) {
            float dtx = dt[0][u] * xv[0][u];
            h0 = fmaf(__expf(dt[0][u] * A0), h0, dtx * Bv[0][u].x);
            h1 = fmaf(__expf(dt[0][u] * A1), h1, dtx * Bv[0][u].y);
            float y = fmaf(h0, Cv[0][u].x, h1 * Cv[0][u].y);
            y += __shfl_down_sync(0xffffffffu, y, 4, 8);
            y += __shfl_down_sync(0xffffffffu, y, 2, 8);
            y += __shfl_down_sync(0xffffffffu, y, 1, 8);
            if (g == 0) yp[l + u] = fmaf(Dd, xv[0][u], y);
        }
        int lp = (l + 8 < LC) ? l + 8 : 0;
        #pragma unroll
        for (int u = 0; u < 4; ++u) {
            int ll = lp + u;
            dt[0][u] = __ldg(dtp + ll);
            xv[0][u] = __ldg(xpp + ll);
            Bv[0][u] = *(const float2*)(rp + (size_t)ll * XD);
            Cv[0][u] = *(const float2*)(rp + (size_t)ll * XD + DS);
        }
        #pragma unroll
        for (int u = 0; u < 4; ++u) {
            float dtx = dt[1][u] * xv[1][u];
            h0 = fmaf(__expf(dt[1][u] * A0), h0, dtx * Bv[1][u].x);
            h1 = fmaf(__expf(dt[1][u] * A1), h1, dtx * Bv[1][u].y);
            float y = fmaf(h0, Cv[1][u].x, h1 * Cv[1][u].y);
            y += __shfl_down_sync(0xffffffffu, y, 4, 8);
            y += __shfl_down_sync(0xffffffffu, y, 2, 8);
            y += __shfl_down_sync(0xffffffffu, y, 1, 8);
            if (g == 0) yp[l + 4 + u] = fmaf(Dd, xv[1][u], y);
        }
    }
}

// ---------------------------------------------------------------------------
// g = y_t * silu(z) -> fp16 single (A operand of out_proj 2-pass GEMM)
// ---------------------------------------------------------------------------
__global__ void gmul_cast_kernel()
{
    __shared__ float sY[32][33];
    const int b = blockIdx.z, d0 = blockIdx.y * 32, l0 = blockIdx.x * 32;
    const int tid = threadIdx.x, tx = tid & 31, ty = tid >> 5;

    #pragma unroll
    for (int i = 0; i < 4; ++i) {
        int dd = ty + i * 8;
        sY[dd][tx] = g_yt[(size_t)(b*DI + d0 + dd) * LL + l0 + tx];
    }
    __syncthreads();
    #pragma unroll
    for (int i = 0; i < 4; ++i) {
        int r = ty + i * 8;
        float z = g_xz[(size_t)(b*LL + l0 + r) * XZW + DI + d0 + tx];
        float v = sY[tx][r] * siluf(z);
        g_gh[(size_t)(b*LL + l0 + r) * DI + d0 + tx] = __float2half_rn(v);
    }
}

// ---------------------------------------------------------------------------
extern "C" void kernel_launch(void* const* d_in, const int* in_sizes, int n_in,
                              void* d_out, int out_size)
{
    const float* x       = (const float*)d_in[0];
    const float* in_proj = (const float*)d_in[1];
    const float* conv_w  = (const float*)d_in[2];
    const float* conv_b  = (const float*)d_in[3];
    const float* x_proj  = (const float*)d_in[4];
    const float* dt_w    = (const float*)d_in[5];
    const float* dt_b    = (const float*)d_in[6];
    const float* A_log   = (const float*)d_in[7];
    const float* Dv      = (const float*)d_in[8];
    const float* out_w   = (const float*)d_in[9];
    float* out = (float*)d_out;

    float *xz, *xpart, *delta;
    __half *xh, *w1h, *w1l, *xph, *xpl, *w3h, *w3l;
    __half *dth, *dtl, *wdh, *wdl, *ghp, *w2h, *w2l;
    cudaGetSymbolAddress((void**)&xz,    g_xz);
    cudaGetSymbolAddress((void**)&xpart, g_xpart);
    cudaGetSymbolAddress((void**)&delta, g_delta);
    cudaGetSymbolAddress((void**)&xh,    g_xh);
    cudaGetSymbolAddress((void**)&w1h,   g_w1h);
    cudaGetSymbolAddress((void**)&w1l,   g_w1l);
    cudaGetSymbolAddress((void**)&xph,   g_xph);
    cudaGetSymbolAddress((void**)&xpl,   g_xpl);
    cudaGetSymbolAddress((void**)&w3h,   g_w3h);
    cudaGetSymbolAddress((void**)&w3l,   g_w3l);
    cudaGetSymbolAddress((void**)&dth,   g_dth);
    cudaGetSymbolAddress((void**)&dtl,   g_dtl);
    cudaGetSymbolAddress((void**)&wdh,   g_wdh);
    cudaGetSymbolAddress((void**)&wdl,   g_wdl);
    cudaGetSymbolAddress((void**)&ghp,   g_gh);
    cudaGetSymbolAddress((void**)&w2h,   g_w2h);
    cudaGetSymbolAddress((void**)&w2l,   g_w2l);

    cudaFuncSetAttribute(hmma2_gemm, cudaFuncAttributeMaxDynamicSharedMemorySize, H2_SMEM);
    cudaFuncSetAttribute(hmma3_gemm, cudaFuncAttributeMaxDynamicSharedMemorySize, H3_SMEM);

    // 0-2) conversions (so in_proj hmma2 sits at launch index 3 for ncu)
    cast_f16<<<(NR*DM/4 + 255)/256, 256>>>(x, xh, NR*DM/4);
    split_f16<<<(XZW*DM/4 + 255)/256, 256>>>(in_proj, w1h, w1l, XZW*DM/4);
    split_f16<<<(DM*DI/4 + 255)/256, 256>>>(out_w, w2h, w2l, DM*DI/4);
    // 3) xz = x @ in_proj_w^T  (2-pass fp16) -> [4096, 4096]
    hmma2_gemm<<<dim3(XZW/128, NR/128), 256, H2_SMEM>>>(xh, w1h, w1l, xz, XZW, DM);
    // 4) conv + silu (fp16 hi/lo xproj-A + fp32 transposed)
    conv_silu_kernel<<<dim3(LL/32, DI/32, BB), 256>>>(conv_w, conv_b);
    // 5) pad+split x_proj_w; split dt_proj_w (fp16)
    split_pad_xw<<<(128*DI/4 + 255)/256, 256>>>(x_proj);
    split_f16<<<(DI*DR/4 + 255)/256, 256>>>(dt_w, wdh, wdl, DI*DR/4);
    // 6) x_dbl partials = x_p @ x_proj_w^T (3-pass fp16, split-K x8)
    hmma3_gemm<<<dim3(1, NR/128, 8), 256, H3_SMEM>>>(
        xph, xpl, w3h, w3l, xpart, 128, DI, DI/8, (size_t)NR*128);
    // 7) reduce partials -> g_xdbl; fp16 hi/lo delta-A cols
    reduce_xdbl<<<(NR*24 + 255)/256, 256>>>();
    // 8) delta raw = x_dbl[:, :64] @ dt_proj_w^T (3-pass fp16)
    hmma3_gemm<<<dim3(DI/128, NR/128, 1), 256, H3_SMEM>>>(
        dth, dtl, wdh, wdl, delta, DI, DR, DR, 0);
    // 9) softplus(delta + bias), transposed
    dtrans_kernel<<<dim3(LL/32, DI/32, BB), 256>>>(dt_b);
    // 10) chunked selective scan (16 chunks of 128)
    scan_pass1<<<dim3((BB*DI)/32, NCH-1), 256>>>(A_log);
    scan_pass2<<<dim3((BB*DI)/32, NCH), 256>>>(A_log, Dv);
    // 11) g = y * silu(z) -> fp16
    gmul_cast_kernel<<<dim3(LL/32, DI/32, BB), 256>>>();
    // 12) out = g @ out_proj_w^T (2-pass fp16)
    hmma2_gemm<<<dim3(DM/128, NR/128), 256, H2_SMEM>>>(ghp, w2h, w2l, out, DM, DI);
}